// round 14
// baseline (speedup 1.0000x reference)
#include <cuda_runtime.h>
#include <cuda_bf16.h>
#include <cuda_fp16.h>
#define NDIM 2304
#define HEADS 8

__device__ __align__(16) char g_wsp[4*2*4*2*16384];
__device__ __align__(16) char g_xt [36*4*2*8192];
__device__ __align__(16) __nv_bfloat16 g_qp[HEADS*NDIM*64];
__device__ __align__(16) __nv_bfloat16 g_kp[HEADS*NDIM*64];
__device__ __align__(16) __half g_vh[256*NDIM];
__device__ __align__(16) float g_po[18*8*2*128*34];

#if defined(__CUDA_ARCH_FEAT_SM103_ALL) || defined(__CUDA_ARCH_FEAT_SM100_ALL)
#define HAS_TC 1
#endif

__device__ __forceinline__ unsigned su32(const void*p){unsigned a;
    asm("{.reg .u64 t; cvta.to.shared.u64 t,%1; cvt.u32.u64 %0,t;}":"=r"(a):"l"(p));return a;}
#define TC_ALLOC(sa,n) asm volatile("tcgen05.alloc.cta_group::1.sync.aligned.shared::cta.b32 [%0],%1;"::"r"(sa),"r"(n):"memory")
#define TC_RELINQ() asm volatile("tcgen05.relinquish_alloc_permit.cta_group::1.sync.aligned;")
#define TC_DEALLOC(t,n) asm volatile("tcgen05.dealloc.cta_group::1.sync.aligned.b32 %0,%1;"::"r"(t),"r"(n))
#define TC_COMMIT(mb) asm volatile("tcgen05.commit.cta_group::1.mbarrier::arrive::one.shared::cluster.b64 [%0];"::"r"(mb):"memory")
#define TC_FA() asm volatile("tcgen05.fence::after_thread_sync;":::"memory")
#define TC_FB() asm volatile("tcgen05.fence::before_thread_sync;":::"memory")
#define TC_WLD() asm volatile("tcgen05.wait::ld.sync.aligned;":::"memory")
#define TC_WST() asm volatile("tcgen05.wait::st.sync.aligned;":::"memory")
#define FPA() asm volatile("fence.proxy.async.shared::cta;":::"memory")
#define MBI(mb,c) asm volatile("mbarrier.init.shared.b64 [%0],%1;"::"r"(mb),"r"(c):"memory")
#define MBW(mb,ph) do{unsigned _d=0;while(!_d){asm volatile("{.reg .pred p;\n mbarrier.try_wait.parity.acquire.cta.shared::cta.b64 p,[%1],%2;\n selp.b32 %0,1,0,p;}":"=r"(_d):"r"(mb),"r"(ph):"memory");}}while(0)
#define TC_LD32(r,a) asm volatile("tcgen05.ld.sync.aligned.32x32b.x32.b32 {%0,%1,%2,%3,%4,%5,%6,%7,%8,%9,%10,%11,%12,%13,%14,%15,%16,%17,%18,%19,%20,%21,%22,%23,%24,%25,%26,%27,%28,%29,%30,%31},[%32];" \
 :"=r"((r)[0]),"=r"((r)[1]),"=r"((r)[2]),"=r"((r)[3]),"=r"((r)[4]),"=r"((r)[5]),"=r"((r)[6]),"=r"((r)[7]),"=r"((r)[8]),"=r"((r)[9]),"=r"((r)[10]),"=r"((r)[11]),"=r"((r)[12]),"=r"((r)[13]),"=r"((r)[14]),"=r"((r)[15]), \
  "=r"((r)[16]),"=r"((r)[17]),"=r"((r)[18]),"=r"((r)[19]),"=r"((r)[20]),"=r"((r)[21]),"=r"((r)[22]),"=r"((r)[23]),"=r"((r)[24]),"=r"((r)[25]),"=r"((r)[26]),"=r"((r)[27]),"=r"((r)[28]),"=r"((r)[29]),"=r"((r)[30]),"=r"((r)[31]):"r"(a))
#define TC_LD1(r0,a) asm volatile("tcgen05.ld.sync.aligned.32x32b.x1.b32 {%0},[%1];":"=r"(r0):"r"(a))
#define TC_ST16(a,r) asm volatile("tcgen05.st.sync.aligned.32x32b.x16.b32 [%0],{%1,%2,%3,%4,%5,%6,%7,%8,%9,%10,%11,%12,%13,%14,%15,%16};" \
 ::"r"(a),"r"((r)[0]),"r"((r)[1]),"r"((r)[2]),"r"((r)[3]),"r"((r)[4]),"r"((r)[5]),"r"((r)[6]),"r"((r)[7]),"r"((r)[8]),"r"((r)[9]),"r"((r)[10]),"r"((r)[11]),"r"((r)[12]),"r"((r)[13]),"r"((r)[14]),"r"((r)[15]):"memory")
#define SWZ(x) ((x)^(((x)>>3)&0x70))
__device__ __forceinline__ unsigned long long mkd(unsigned a){
    return ((2ull<<61)|(1ull<<46)|(64ull<<32)|(1ull<<16))|((unsigned long long)(a>>4)&0x3FFF);}
__device__ __forceinline__ void mma_ss(unsigned d,unsigned long long a,unsigned long long b,unsigned id,unsigned en){
    asm volatile("{.reg .pred p;\n setp.ne.u32 p,%5,0;\n tcgen05.mma.cta_group::1.kind::f16 [%0],%1,%2,%3,{%4,%4,%4,%4},p;}"
    ::"r"(d),"l"(a),"l"(b),"r"(id),"r"(0u),"r"(en):"memory");}
__device__ __forceinline__ void mma_ts(unsigned d,unsigned a,unsigned long long b,unsigned id,unsigned en){
    asm volatile("{.reg .pred p;\n setp.ne.u32 p,%5,0;\n tcgen05.mma.cta_group::1.kind::f16 [%0],[%1],%2,%3,{%4,%4,%4,%4},p;}"
    ::"r"(d),"r"(a),"l"(b),"r"(id),"r"(0u),"r"(en):"memory");}
__device__ __forceinline__ float ex2f(float x){float y;asm("ex2.approx.ftz.f32 %0,%1;":"=f"(y):"f"(x));return y;}
__device__ __forceinline__ float rcpf(float x){float y;asm("rcp.approx.ftz.f32 %0,%1;":"=f"(y):"f"(x));return y;}
__device__ __forceinline__ unsigned f16p(float lo,float hi){unsigned r;
    asm("cvt.rn.f16x2.f32 %0,%1,%2;":"=r"(r):"f"(hi),"f"(lo));return r;}
#define IDS 0x8100490u
#define IDS32 0x8080490u
#define IDS16 0x8040490u
#define IDP 0x80A0010u

// ---------------- prep (merged W + X) ----------------
__global__ void __launch_bounds__(256)
prep_all(const float* __restrict__ x,const float* __restrict__ Wq,
         const float* __restrict__ Wk,const float* __restrict__ Wv,
         const float* __restrict__ Wp){
    const int b=blockIdx.x,tid=threadIdx.x;
    if(b<32){
        const int z=b>>3,mh=(b>>2)&1,kc=b&3;
        const float* W=(z==0)?Wq:(z==1)?Wk:(z==2)?Wv:Wp;
        char* img=g_wsp+(unsigned)(((z*2+mh)*4+kc)*2)*16384u;
        int r=tid>>1,c0=(tid&1)*32;
#pragma unroll
        for(int cc=0;cc<32;cc++){
            int c=c0+cc;
            float v=W[(mh*128+r)*256+kc*64+c];
            __nv_bfloat16 hi=__float2bfloat16(v);
            unsigned off=SWZ((unsigned)(r*128+c*2));
            *(__nv_bfloat16*)(img+off)=hi;
            *(__nv_bfloat16*)(img+16384+off)=__float2bfloat16(v-__bfloat162float(hi));
        }
    }else{
        const int q=b-32,nt=q>>2,kc=q&3;
        char* img=g_xt+(unsigned)((nt*4+kc)*2)*8192u;
        int c=tid>>2,r0=(tid&3)*16;
#pragma unroll
        for(int rr=0;rr<16;rr++){
            int r=r0+rr;
            float v=x[(kc*64+c)*NDIM+nt*64+r];
            __nv_bfloat16 hi=__float2bfloat16(v);
            unsigned off=SWZ((unsigned)(r*128+c*2));
            *(__nv_bfloat16*)(img+off)=hi;
            *(__nv_bfloat16*)(img+8192+off)=__float2bfloat16(v-__bfloat162float(hi));
        }
    }
}

// ---------------- QKV GEMM: load-all, single commit. 128o x 32n ----------------
#define GM2 163904
__global__ void __launch_bounds__(256,1)
tc_gemm(const char* __restrict__ Ab,const char* __restrict__ Bb,
        const float* __restrict__ b0,const float* __restrict__ b1,
        const float* __restrict__ b2){
    const int z=blockIdx.z,mh=blockIdx.y,nt2=blockIdx.x,tid=threadIdx.x;
    const float* bb=(z==0)?b0:(z==1)?b1:b2;
#ifdef HAS_TC
    extern __shared__ char sm[];
    const unsigned smb=su32(sm);
    const int wid=tid>>5,lid=tid&31;
    if(wid==0){ TC_ALLOC(smb+163840,128); TC_RELINQ(); }
    if(tid==0) MBI(smb+163848,1);
    const char* Abase=Ab+(unsigned)((z*2+mh)*4*2)*16384u;
    const int nt=nt2>>1,sub=nt2&1;
    // A: 128 KB contiguous
#pragma unroll
    for(int i=0;i<32;i++) *(uint4*)(sm+tid*16+i*4096)=*(const uint4*)(Abase+tid*16+i*4096);
    // B: per chunk, 32-row half (4 KB hi + 4 KB lo)
#pragma unroll
    for(int kc=0;kc<4;kc++){
        const char* Bs=Bb+(unsigned)((nt*4+kc)*2)*8192u+(unsigned)sub*4096u;
        *(uint4*)(sm+131072+kc*8192+tid*16)=*(const uint4*)(Bs+tid*16);
        *(uint4*)(sm+131072+kc*8192+4096+tid*16)=*(const uint4*)(Bs+8192+tid*16);
    }
    FPA(); __syncthreads();
    unsigned tmem; asm volatile("ld.shared.b32 %0,[%1];":"=r"(tmem):"r"(smb+163840));
    if(tid==0){
#pragma unroll
        for(int kc=0;kc<4;kc++){
            unsigned long long ah=mkd(smb+kc*32768),al=ah+1024;
            unsigned long long bh=mkd(smb+131072+kc*8192),bl=bh+256;
#pragma unroll
            for(int ks=0;ks<4;ks++){
                unsigned long long o2=ks*2;
                mma_ss(tmem,ah+o2,bh+o2,IDS32,(kc|ks)!=0);
                mma_ss(tmem,ah+o2,bl+o2,IDS32,1);
                mma_ss(tmem,al+o2,bh+o2,IDS32,1);
            }
        }
        TC_COMMIT(smb+163848);
    }
    MBW(smb+163848,0);
    TC_FA();
    const int sp=wid&3,hf=wid>>2;
    if(hf==0){
        unsigned sr[32];
        TC_LD32(sr,tmem+((unsigned)sp<<21)); TC_WLD();
        const int o=mh*128+sp*32+lid;
        const float bv=bb[o];
        if(z==2){
            unsigned hw[16];
#pragma unroll
            for(int jj=0;jj<16;jj++)
                hw[jj]=f16p(__uint_as_float(sr[2*jj])+bv,__uint_as_float(sr[2*jj+1])+bv);
            uint4* dst=(uint4*)(g_vh+(unsigned)o*NDIM+nt2*32);
#pragma unroll
            for(int i=0;i<4;i++) dst[i]=make_uint4(hw[4*i],hw[4*i+1],hw[4*i+2],hw[4*i+3]);
        }else{
            const float CQ=0.17677669529663687f*1.4426950408889634f;
            const float cm=(z==0)?CQ:1.f;
            __nv_bfloat16* stg=(__nv_bfloat16*)sm;
#pragma unroll
            for(int j=0;j<32;j++){
                float vv=(__uint_as_float(sr[j])+bv)*cm;
                __nv_bfloat16 hi=__float2bfloat16(vv);
                stg[(j*4+sp)*64+lid]=hi;
                stg[(j*4+sp)*64+32+lid]=__float2bfloat16(vv-__bfloat162float(hi));
            }
        }
    }
    __syncthreads();
    if(z<2){
        const int r=tid>>3,p=(tid&7)>>1,hh=tid&1;
        const __nv_bfloat16* stg=(const __nv_bfloat16*)sm;
        __nv_bfloat16* dst=((z==0)?g_qp:g_kp)+(unsigned)(mh*4+p)*(NDIM*64)
                           +(unsigned)(nt2*32+r)*64+hh*32;
        const uint4* src=(const uint4*)(stg+(r*4+p)*64+hh*32);
#pragma unroll
        for(int i=0;i<4;i++) ((uint4*)dst)[i]=src[i];
    }
    __syncthreads();
    if(wid==0) TC_DEALLOC(tmem,128);
#else
    for(int it=tid;it<4096;it+=256){
        int oL=it>>5,j=it&31,o=mh*128+oL,n=nt2*32+j;
        float acc=0.f;
        for(int kc=0;kc<4;kc++){
            const char* Ai=Ab+(unsigned)(((z*2+mh)*4+kc)*2)*16384u;
            const char* Bi=Bb+(unsigned)(((nt2>>1)*4+kc)*2)*8192u+(unsigned)(nt2&1)*4096u;
            for(int c=0;c<64;c++){
                unsigned ao=SWZ((unsigned)(oL*128+c*2)),bo2=SWZ((unsigned)(j*128+c*2));
                float a=__bfloat162float(*(const __nv_bfloat16*)(Ai+ao))
                       +__bfloat162float(*(const __nv_bfloat16*)(Ai+16384+ao));
                float bvv=__bfloat162float(*(const __nv_bfloat16*)(Bi+bo2))
                         +__bfloat162float(*(const __nv_bfloat16*)(Bi+8192+bo2));
                acc+=a*bvv;
            }
        }
        float val=acc+bb[o];
        if(z==2) g_vh[o*NDIM+n]=__float2half(val);
        else{
            const float CQ=0.17677669529663687f*1.4426950408889634f;
            float vv=val*((z==0)?CQ:1.f);
            __nv_bfloat16 hi=__float2bfloat16(vv);
            __nv_bfloat16* base=((z==0)?g_qp:g_kp)+(o>>5)*(NDIM*64);
            base[n*64+(o&31)]=hi;
            base[n*64+32+(o&31)]=__float2bfloat16(vv-__bfloat162float(hi));
        }
    }
#endif
}

// ---------------- proj GEMM: load-all, single commit, 2 x (128o x 16n) tiles ----------------
__global__ void __launch_bounds__(256,1)
tc_proj(const char* __restrict__ Ab,const float* __restrict__ bp,
        float* __restrict__ outp){
    const int mh=blockIdx.y,ntp=blockIdx.x,tid=threadIdx.x;
#ifdef HAS_TC
    extern __shared__ char sm[];
    const unsigned smb=su32(sm);
    const int wid=tid>>5,lid=tid&31;
    if(wid==0){ TC_ALLOC(smb+163840,128); TC_RELINQ(); }
    if(tid==0) MBI(smb+163848,1);
    const char* Abase=Ab+(unsigned)((6+mh)*4*2)*16384u;
#pragma unroll
    for(int i=0;i<32;i++) *(uint4*)(sm+tid*16+i*4096)=*(const uint4*)(Abase+tid*16+i*4096);
    // B: 2 tiles x 4 chunks x (2K hi + 2K lo), built from partials
    const int nloc=tid>>4,c0=(tid&15)*4;
#pragma unroll
    for(int tt=0;tt<2;tt++){
        const int npo=ntp*32+tt*16+nloc,qt=npo>>7,nl=npo&127;
        const float* pl0=g_po+(unsigned)(((qt*8+0)*2+0)*128+nl)*34u;
        const float* pl1=g_po+(unsigned)(((qt*8+0)*2+1)*128+nl)*34u;
#pragma unroll
        for(int kc=0;kc<4;kc++){
            int gc=kc*64+c0,Hh=gc>>5,d0=gc&31;
            const float* p0=pl0+(unsigned)(Hh*2)*128u*34u;
            const float* p1=pl1+(unsigned)(Hh*2)*128u*34u;
            float inv=rcpf(p0[32]+p1[32]);
            char* dst=sm+131072+tt*16384+kc*4096;
#pragma unroll
            for(int i=0;i<4;i++){
                float v=(p0[d0+i]+p1[d0+i])*inv;
                __nv_bfloat16 hi=__float2bfloat16(v);
                unsigned off=SWZ((unsigned)(nloc*128+(c0+i)*2));
                *(__nv_bfloat16*)(dst+off)=hi;
                *(__nv_bfloat16*)(dst+2048+off)=__float2bfloat16(v-__bfloat162float(hi));
            }
        }
    }
    FPA(); __syncthreads();
    unsigned tmem; asm volatile("ld.shared.b32 %0,[%1];":"=r"(tmem):"r"(smb+163840));
    if(tid==0){
#pragma unroll
        for(int tt=0;tt<2;tt++){
            unsigned dD=tmem+tt*16;
#pragma unroll
            for(int kc=0;kc<4;kc++){
                unsigned long long ah=mkd(smb+kc*32768),al=ah+1024;
                unsigned long long bh=mkd(smb+131072+tt*16384+kc*4096),bl=bh+128;
#pragma unroll
                for(int ks=0;ks<4;ks++){
                    unsigned long long o2=ks*2;
                    mma_ss(dD,ah+o2,bh+o2,IDS16,(kc|ks)!=0);
                    mma_ss(dD,ah+o2,bl+o2,IDS16,1);
                    mma_ss(dD,al+o2,bh+o2,IDS16,1);
                }
            }
        }
        TC_COMMIT(smb+163848);
    }
    MBW(smb+163848,0);
    TC_FA();
    const int sp=wid&3,hf=wid>>2;
    if(hf==0){
        unsigned sr[32];
        TC_LD32(sr,tmem+((unsigned)sp<<21)); TC_WLD();
        const int o=mh*128+sp*32+lid;
        const float bv=bp[o];
#pragma unroll
        for(int j=0;j<32;j++) outp[o*NDIM+ntp*32+j]=__uint_as_float(sr[j])+bv;
    }
    __syncthreads();
    if(wid==0) TC_DEALLOC(tmem,128);
#else
    for(int it=tid;it<4096;it+=256){
        int oL=it>>5,j=it&31,o=mh*128+oL,n=ntp*32+j;
        float acc=0.f;
        for(int kc=0;kc<4;kc++){
            const char* Ai=Ab+(unsigned)(((6+mh)*4+kc)*2)*16384u;
            for(int c=0;c<64;c++){
                unsigned ao=SWZ((unsigned)(oL*128+c*2));
                float a=__bfloat162float(*(const __nv_bfloat16*)(Ai+ao))
                       +__bfloat162float(*(const __nv_bfloat16*)(Ai+16384+ao));
                int qt2=n>>7,nl2=n&127,cg2=kc*64+c,Hh=cg2>>5,d=cg2&31;
                const float* p0=g_po+(unsigned)(((qt2*8+Hh)*2+0)*128+nl2)*34u;
                const float* p1=g_po+(unsigned)(((qt2*8+Hh)*2+1)*128+nl2)*34u;
                acc+=a*(p0[d]+p1[d])/(p0[32]+p1[32]);
            }
        }
        outp[o*NDIM+n]=acc+bp[o];
    }
#endif
}

// ---------------- attention: split-KV + pipelined S (unchanged from R13) ----------------
#define SM_B 64
#define SM_Q 36864
#define SM_K 53248
#define SM_V 77824
#define SM_TOT 98304
#define TPC 18

#ifdef HAS_TC
__device__ __forceinline__ void issue_s(unsigned tmem,unsigned smb,int t){
    unsigned long long kd=mkd(smb+SM_K+(t%3)*8192);
    unsigned long long qd=mkd(smb+SM_Q);
    unsigned tS=tmem+64+(t&1)*64;
    mma_ss(tS,qd+0,kd+0,IDS,0); mma_ss(tS,qd+2,kd+2,IDS,1);
    mma_ss(tS,qd+0,kd+4,IDS,1); mma_ss(tS,qd+2,kd+6,IDS,1);
    mma_ss(tS,qd+4,kd+0,IDS,1); mma_ss(tS,qd+6,kd+2,IDS,1);
    TC_COMMIT(smb+8+8*(t&1));
}
#endif

__global__ void __launch_bounds__(256,2)
attn_kernel(const float* __restrict__ emb){
    extern __shared__ char sm[];
#ifdef HAS_TC
    const unsigned smb=su32(sm);
    const int tid=threadIdx.x,wid=tid>>5,lid=tid&31;
    const int H=blockIdx.y,n0=blockIdx.x*128,half=blockIdx.z;
    const int tbase=half*TPC;
    float* bias=(float*)(sm+SM_B);
    if(wid==0){ TC_ALLOC(smb,256); TC_RELINQ(); }
    if(tid==0){MBI(smb+8,1);MBI(smb+16,1);MBI(smb+24,1);MBI(smb+32,1);}
    for(int i=tid;i<9025;i+=256){
        int a=i/95,b=i-a*95,dx=a-47,dy=b-47;
        if(dx<0)dx=-dx; if(dy<0)dy=-dy;
        bias[i]=(dx<=5&&dy<=5)?emb[(dx*6+dy)*8+H]*1.4426950408889634f:0.f;
    }
    const __nv_bfloat16* qp=g_qp+H*(NDIM*64);
    const __nv_bfloat16* kp=g_kp+H*(NDIM*64);
#pragma unroll
    for(int e=0;e<4;e++){
        int idx=tid+e*256,r=idx>>3,c=(idx&7)*16;
        uint4 v=*(const uint4*)((const char*)(qp+(n0+r)*64)+c);
        *(uint4*)(sm+SM_Q+SWZ(r*128+c))=v;
    }
    {
        int b=tid>>6,i=tid&63,d=32+(i>>3),c=(i&7)*16;
        unsigned w=(d==32)?0x3C003C00u:0u;
        *(uint4*)(sm+SM_V+b*5120+SWZ(d*128+c))=make_uint4(w,w,w,w);
    }
    const int lj=tid>>3, lc=(tid&7)*16, ld=tid>>3;
#pragma unroll
    for(int t=0;t<2;t++){
        int m0=(tbase+t)*64;
        uint4 k0=*(const uint4*)((const char*)(kp+(m0+lj)*64)+lc);
        uint4 k1=*(const uint4*)((const char*)(kp+(m0+lj+32)*64)+lc);
        uint4 vv=*(const uint4*)((const char*)(g_vh+(H*32+ld)*NDIM+m0)+lc);
        *(uint4*)(sm+SM_K+t*8192+SWZ(lj*128+lc))=k0;
        *(uint4*)(sm+SM_K+t*8192+SWZ((lj+32)*128+lc))=k1;
        *(uint4*)(sm+SM_V+t*5120+SWZ(ld*128+lc))=vv;
    }
    FPA(); __syncthreads();
    unsigned tmem; asm volatile("ld.shared.b32 %0,[%1];":"=r"(tmem):"r"(smb));
    if(tid==0) issue_s(tmem,smb,0);
    const int sp=wid&3,hf=wid>>2;
    const unsigned spoff=(unsigned)sp<<21;
    const int n=n0+sp*32+lid,xn=n/48,yn=n-xn*48;
    const float* bp=bias+xn*95+yn+4512;

    for(int t=0;t<TPC;t++){
        if(t<TPC-1&&tid==0) issue_s(tmem,smb,t+1);
        uint4 k0,k1,vv; const bool pf=(t<TPC-2);
        if(pf){
            int m0=(tbase+t+2)*64;
            k0=*(const uint4*)((const char*)(kp+(m0+lj)*64)+lc);
            k1=*(const uint4*)((const char*)(kp+(m0+lj+32)*64)+lc);
            vv=*(const uint4*)((const char*)(g_vh+(H*32+ld)*NDIM+m0)+lc);
        }
        if(t>=2) MBW(smb+24+8*(t&1),((t-2)>>1)&1);
        MBW(smb+8+8*(t&1),(t>>1)&1); TC_FA();
        unsigned sr[32];
        TC_LD32(sr,tmem+64+(t&1)*64+hf*32+spoff); TC_WLD();
        const int mc=(tbase+t)*64+hf*32;
        unsigned pk[16];
#pragma unroll
        for(int jj=0;jj<16;jj++){
            int m0_=mc+2*jj,m1_=m0_+1;
            int x0=(m0_*2731)>>17,x1=(m1_*2731)>>17;
            float p0=ex2f(__uint_as_float(sr[2*jj])+bp[-(m0_+47*x0)]);
            float p1=ex2f(__uint_as_float(sr[2*jj+1])+bp[-(m1_+47*x1)]);
            pk[jj]=f16p(p0,p1);
        }
        const unsigned pbase=tmem+192+(t&1)*32;
        TC_ST16(pbase+hf*16+spoff,pk); TC_WST();
        if(pf){
            int ko=SM_K+((t+2)%3)*8192, vo=SM_V+((t+2)%4)*5120;
            *(uint4*)(sm+ko+SWZ(lj*128+lc))=k0;
            *(uint4*)(sm+ko+SWZ((lj+32)*128+lc))=k1;
            *(uint4*)(sm+vo+SWZ(ld*128+lc))=vv;
        }
        TC_FB(); FPA(); __syncthreads();
        if(tid==0){
            TC_FA();
            unsigned long long vd=mkd(smb+SM_V+(t%4)*5120);
#pragma unroll
            for(int k=0;k<4;k++) mma_ts(tmem,pbase+k*8,vd+k*2,IDP,(t+k)>0);
            TC_COMMIT(smb+24+8*(t&1));
        }
    }
    MBW(smb+24,0); MBW(smb+32,0);
    TC_FA();
    if(hf==0){
        unsigned od[32],lr;
        TC_LD32(od,tmem+spoff); TC_LD1(lr,tmem+32+spoff); TC_WLD();
        float* po=g_po+(unsigned)(((blockIdx.x*8+H)*2+half)*128+sp*32+lid)*34u;
#pragma unroll
        for(int d=0;d<32;d++) po[d]=__uint_as_float(od[d]);
        po[32]=__uint_as_float(lr);
    }
    __syncthreads();
    if(wid==0) TC_DEALLOC(tmem,256);
#else
    const int tid=threadIdx.x,H=blockIdx.y,n0=blockIdx.x*128,half=blockIdx.z;
    if(tid<128){
        int n=n0+tid,xn=n/48,yn=n-48*xn;
        const __nv_bfloat16* qr=g_qp+H*(NDIM*64)+n*64;
        float qv[32],o[32],l=0.f;
#pragma unroll
        for(int d=0;d<32;d++){qv[d]=__bfloat162float(qr[d])+__bfloat162float(qr[32+d]);o[d]=0.f;}
        for(int mt=0;mt<TPC*64;mt++){
            int m=half*TPC*64+mt;
            const __nv_bfloat16* kr=g_kp+H*(NDIM*64)+m*64;
            float s=0.f;
            for(int d=0;d<32;d++) s+=qv[d]*(__bfloat162float(kr[d])+__bfloat162float(kr[32+d]));
            int xm=m/48,ym=m-48*xm,dx=xn-xm,dy=yn-ym;
            if(dx<0)dx=-dx; if(dy<0)dy=-dy;
            float b=(dx<6&&dy<6)?emb[(dx*6+dy)*8+H]*1.4426950408889634f:0.f;
            float p=exp2f(s+b); l+=p;
            for(int d=0;d<32;d++) o[d]+=p*__half2float(g_vh[(H*32+d)*NDIM+m]);
        }
        float* po=g_po+(unsigned)(((blockIdx.x*8+H)*2+half)*128+tid)*34u;
        for(int d=0;d<32;d++) po[d]=o[d];
        po[32]=l;
    }
#endif
}

extern "C" void kernel_launch(void* const* d_in,const int* in_sizes,int n_in,
                              void* d_out,int out_size){
    const float* x  =(const float*)d_in[0];
    const float* Wq =(const float*)d_in[1]; const float* bq=(const float*)d_in[2];
    const float* Wk =(const float*)d_in[3]; const float* bk=(const float*)d_in[4];
    const float* Wv =(const float*)d_in[5]; const float* bv=(const float*)d_in[6];
    const float* Wp =(const float*)d_in[7]; const float* bp=(const float*)d_in[8];
    const float* emb=(const float*)d_in[9];
    float* out=(float*)d_out;
    char* wsp; char* xt;
    cudaGetSymbolAddress((void**)&wsp,g_wsp);
    cudaGetSymbolAddress((void**)&xt,g_xt);
    cudaFuncSetAttribute(tc_gemm,cudaFuncAttributeMaxDynamicSharedMemorySize,GM2);
    cudaFuncSetAttribute(tc_proj,cudaFuncAttributeMaxDynamicSharedMemorySize,GM2);
    cudaFuncSetAttribute(attn_kernel,cudaFuncAttributeMaxDynamicSharedMemorySize,SM_TOT);
    prep_all<<<176,256>>>(x,Wq,Wk,Wv,Wp);
    tc_gemm<<<dim3(72,2,3),256,GM2>>>(wsp,xt,bq,bk,bv);
    attn_kernel<<<dim3(18,HEADS,2),256,SM_TOT>>>(emb);
    tc_proj<<<dim3(72,2),256,GM2>>>(wsp,bp,out);
}

// round 15
// speedup vs baseline: 1.0513x; 1.0513x over previous
#include <cuda_runtime.h>
#include <cuda_bf16.h>
#include <cuda_fp16.h>
#define NDIM 2304
#define HEADS 8

__device__ __align__(16) char g_wsp[4*2*4*2*16384];
__device__ __align__(16) char g_xt [36*4*2*8192];
__device__ __align__(16) __nv_bfloat16 g_qp[HEADS*NDIM*64];
__device__ __align__(16) __nv_bfloat16 g_kp[HEADS*NDIM*64];
__device__ __align__(16) __half g_vh[256*NDIM];
__device__ __align__(16) float g_po[18*8*2*128*34];

#if defined(__CUDA_ARCH_FEAT_SM103_ALL) || defined(__CUDA_ARCH_FEAT_SM100_ALL)
#define HAS_TC 1
#endif

__device__ __forceinline__ unsigned su32(const void*p){unsigned a;
    asm("{.reg .u64 t; cvta.to.shared.u64 t,%1; cvt.u32.u64 %0,t;}":"=r"(a):"l"(p));return a;}
#define TC_ALLOC(sa,n) asm volatile("tcgen05.alloc.cta_group::1.sync.aligned.shared::cta.b32 [%0],%1;"::"r"(sa),"r"(n):"memory")
#define TC_RELINQ() asm volatile("tcgen05.relinquish_alloc_permit.cta_group::1.sync.aligned;")
#define TC_DEALLOC(t,n) asm volatile("tcgen05.dealloc.cta_group::1.sync.aligned.b32 %0,%1;"::"r"(t),"r"(n))
#define TC_COMMIT(mb) asm volatile("tcgen05.commit.cta_group::1.mbarrier::arrive::one.shared::cluster.b64 [%0];"::"r"(mb):"memory")
#define TC_FA() asm volatile("tcgen05.fence::after_thread_sync;":::"memory")
#define TC_FB() asm volatile("tcgen05.fence::before_thread_sync;":::"memory")
#define TC_WLD() asm volatile("tcgen05.wait::ld.sync.aligned;":::"memory")
#define TC_WST() asm volatile("tcgen05.wait::st.sync.aligned;":::"memory")
#define FPA() asm volatile("fence.proxy.async.shared::cta;":::"memory")
#define MBI(mb,c) asm volatile("mbarrier.init.shared.b64 [%0],%1;"::"r"(mb),"r"(c):"memory")
#define MBX(mb,b) asm volatile("mbarrier.arrive.expect_tx.shared.b64 _, [%0], %1;"::"r"(mb),"r"(b):"memory")
#define BULK(dst,src,sz,mb) asm volatile("cp.async.bulk.shared::cta.global.mbarrier::complete_tx::bytes [%0], [%1], %2, [%3];"::"r"(dst),"l"(src),"r"(sz),"r"(mb):"memory")
#define MBW(mb,ph) do{unsigned _d=0;while(!_d){asm volatile("{.reg .pred p;\n mbarrier.try_wait.parity.acquire.cta.shared::cta.b64 p,[%1],%2;\n selp.b32 %0,1,0,p;}":"=r"(_d):"r"(mb),"r"(ph):"memory");}}while(0)
#define TC_LD32(r,a) asm volatile("tcgen05.ld.sync.aligned.32x32b.x32.b32 {%0,%1,%2,%3,%4,%5,%6,%7,%8,%9,%10,%11,%12,%13,%14,%15,%16,%17,%18,%19,%20,%21,%22,%23,%24,%25,%26,%27,%28,%29,%30,%31},[%32];" \
 :"=r"((r)[0]),"=r"((r)[1]),"=r"((r)[2]),"=r"((r)[3]),"=r"((r)[4]),"=r"((r)[5]),"=r"((r)[6]),"=r"((r)[7]),"=r"((r)[8]),"=r"((r)[9]),"=r"((r)[10]),"=r"((r)[11]),"=r"((r)[12]),"=r"((r)[13]),"=r"((r)[14]),"=r"((r)[15]), \
  "=r"((r)[16]),"=r"((r)[17]),"=r"((r)[18]),"=r"((r)[19]),"=r"((r)[20]),"=r"((r)[21]),"=r"((r)[22]),"=r"((r)[23]),"=r"((r)[24]),"=r"((r)[25]),"=r"((r)[26]),"=r"((r)[27]),"=r"((r)[28]),"=r"((r)[29]),"=r"((r)[30]),"=r"((r)[31]):"r"(a))
#define TC_LD1(r0,a) asm volatile("tcgen05.ld.sync.aligned.32x32b.x1.b32 {%0},[%1];":"=r"(r0):"r"(a))
#define TC_ST16(a,r) asm volatile("tcgen05.st.sync.aligned.32x32b.x16.b32 [%0],{%1,%2,%3,%4,%5,%6,%7,%8,%9,%10,%11,%12,%13,%14,%15,%16};" \
 ::"r"(a),"r"((r)[0]),"r"((r)[1]),"r"((r)[2]),"r"((r)[3]),"r"((r)[4]),"r"((r)[5]),"r"((r)[6]),"r"((r)[7]),"r"((r)[8]),"r"((r)[9]),"r"((r)[10]),"r"((r)[11]),"r"((r)[12]),"r"((r)[13]),"r"((r)[14]),"r"((r)[15]):"memory")
#define SWZ(x) ((x)^(((x)>>3)&0x70))
__device__ __forceinline__ unsigned long long mkd(unsigned a){
    return ((2ull<<61)|(1ull<<46)|(64ull<<32)|(1ull<<16))|((unsigned long long)(a>>4)&0x3FFF);}
__device__ __forceinline__ void mma_ss(unsigned d,unsigned long long a,unsigned long long b,unsigned id,unsigned en){
    asm volatile("{.reg .pred p;\n setp.ne.u32 p,%5,0;\n tcgen05.mma.cta_group::1.kind::f16 [%0],%1,%2,%3,{%4,%4,%4,%4},p;}"
    ::"r"(d),"l"(a),"l"(b),"r"(id),"r"(0u),"r"(en):"memory");}
__device__ __forceinline__ void mma_ts(unsigned d,unsigned a,unsigned long long b,unsigned id,unsigned en){
    asm volatile("{.reg .pred p;\n setp.ne.u32 p,%5,0;\n tcgen05.mma.cta_group::1.kind::f16 [%0],[%1],%2,%3,{%4,%4,%4,%4},p;}"
    ::"r"(d),"r"(a),"l"(b),"r"(id),"r"(0u),"r"(en):"memory");}
__device__ __forceinline__ float ex2f(float x){float y;asm("ex2.approx.ftz.f32 %0,%1;":"=f"(y):"f"(x));return y;}
__device__ __forceinline__ float rcpf(float x){float y;asm("rcp.approx.ftz.f32 %0,%1;":"=f"(y):"f"(x));return y;}
__device__ __forceinline__ unsigned f16p(float lo,float hi){unsigned r;
    asm("cvt.rn.f16x2.f32 %0,%1,%2;":"=r"(r):"f"(hi),"f"(lo));return r;}
#define IDS 0x8100490u
#define IDS32 0x8080490u
#define IDS16 0x8040490u
#define IDP 0x80A0010u

// ---------------- prep (merged W + X) ----------------
__global__ void __launch_bounds__(256)
prep_all(const float* __restrict__ x,const float* __restrict__ Wq,
         const float* __restrict__ Wk,const float* __restrict__ Wv,
         const float* __restrict__ Wp){
    const int b=blockIdx.x,tid=threadIdx.x;
    if(b<32){
        const int z=b>>3,mh=(b>>2)&1,kc=b&3;
        const float* W=(z==0)?Wq:(z==1)?Wk:(z==2)?Wv:Wp;
        char* img=g_wsp+(unsigned)(((z*2+mh)*4+kc)*2)*16384u;
        int r=tid>>1,c0=(tid&1)*32;
#pragma unroll
        for(int cc=0;cc<32;cc++){
            int c=c0+cc;
            float v=W[(mh*128+r)*256+kc*64+c];
            __nv_bfloat16 hi=__float2bfloat16(v);
            unsigned off=SWZ((unsigned)(r*128+c*2));
            *(__nv_bfloat16*)(img+off)=hi;
            *(__nv_bfloat16*)(img+16384+off)=__float2bfloat16(v-__bfloat162float(hi));
        }
    }else{
        const int q=b-32,nt=q>>2,kc=q&3;
        char* img=g_xt+(unsigned)((nt*4+kc)*2)*8192u;
        int c=tid>>2,r0=(tid&3)*16;
#pragma unroll
        for(int rr=0;rr<16;rr++){
            int r=r0+rr;
            float v=x[(kc*64+c)*NDIM+nt*64+r];
            __nv_bfloat16 hi=__float2bfloat16(v);
            unsigned off=SWZ((unsigned)(r*128+c*2));
            *(__nv_bfloat16*)(img+off)=hi;
            *(__nv_bfloat16*)(img+8192+off)=__float2bfloat16(v-__bfloat162float(hi));
        }
    }
}

// ---------------- QKV GEMM: bulk-copy A+B, single commit. 128o x 32n ----------------
#define GM2 163904
__global__ void __launch_bounds__(256,1)
tc_gemm(const char* __restrict__ Ab,const char* __restrict__ Bb,
        const float* __restrict__ b0,const float* __restrict__ b1,
        const float* __restrict__ b2){
    const int z=blockIdx.z,mh=blockIdx.y,nt2=blockIdx.x,tid=threadIdx.x;
    const float* bb=(z==0)?b0:(z==1)?b1:b2;
#ifdef HAS_TC
    extern __shared__ char sm[];
    const unsigned smb=su32(sm);
    const int wid=tid>>5,lid=tid&31;
    if(wid==0){ TC_ALLOC(smb+163840,128); TC_RELINQ(); }
    if(tid==0){ MBI(smb+163848,1); MBI(smb+163856,1); }
    __syncthreads();
    const char* Abase=Ab+(unsigned)((z*2+mh)*4*2)*16384u;
    const int nt=nt2>>1,sub=nt2&1;
    if(tid==0){
        MBX(smb+163848,163840u);
        BULK(smb,Abase,131072u,smb+163848);
#pragma unroll
        for(int kc=0;kc<4;kc++){
            const char* Bs=Bb+(unsigned)((nt*4+kc)*2)*8192u+(unsigned)sub*4096u;
            BULK(smb+131072+kc*8192,Bs,4096u,smb+163848);
            BULK(smb+131072+kc*8192+4096,Bs+8192,4096u,smb+163848);
        }
    }
    unsigned tmem; asm volatile("ld.shared.b32 %0,[%1];":"=r"(tmem):"r"(smb+163840));
    MBW(smb+163848,0);
    if(tid==0){
#pragma unroll
        for(int kc=0;kc<4;kc++){
            unsigned long long ah=mkd(smb+kc*32768),al=ah+1024;
            unsigned long long bh=mkd(smb+131072+kc*8192),bl=bh+256;
#pragma unroll
            for(int ks=0;ks<4;ks++){
                unsigned long long o2=ks*2;
                mma_ss(tmem,ah+o2,bh+o2,IDS32,(kc|ks)!=0);
                mma_ss(tmem,ah+o2,bl+o2,IDS32,1);
                mma_ss(tmem,al+o2,bh+o2,IDS32,1);
            }
        }
        TC_COMMIT(smb+163856);
    }
    MBW(smb+163856,0);
    TC_FA();
    const int sp=wid&3,hf=wid>>2;
    if(hf==0){
        unsigned sr[32];
        TC_LD32(sr,tmem+((unsigned)sp<<21)); TC_WLD();
        const int o=mh*128+sp*32+lid;
        const float bv=bb[o];
        if(z==2){
            unsigned hw[16];
#pragma unroll
            for(int jj=0;jj<16;jj++)
                hw[jj]=f16p(__uint_as_float(sr[2*jj])+bv,__uint_as_float(sr[2*jj+1])+bv);
            uint4* dst=(uint4*)(g_vh+(unsigned)o*NDIM+nt2*32);
#pragma unroll
            for(int i=0;i<4;i++) dst[i]=make_uint4(hw[4*i],hw[4*i+1],hw[4*i+2],hw[4*i+3]);
        }else{
            const float CQ=0.17677669529663687f*1.4426950408889634f;
            const float cm=(z==0)?CQ:1.f;
            __nv_bfloat16* stg=(__nv_bfloat16*)sm;
#pragma unroll
            for(int j=0;j<32;j++){
                float vv=(__uint_as_float(sr[j])+bv)*cm;
                __nv_bfloat16 hi=__float2bfloat16(vv);
                stg[(j*4+sp)*64+lid]=hi;
                stg[(j*4+sp)*64+32+lid]=__float2bfloat16(vv-__bfloat162float(hi));
            }
        }
    }
    __syncthreads();
    if(z<2){
        const int r=tid>>3,p=(tid&7)>>1,hh=tid&1;
        const __nv_bfloat16* stg=(const __nv_bfloat16*)sm;
        __nv_bfloat16* dst=((z==0)?g_qp:g_kp)+(unsigned)(mh*4+p)*(NDIM*64)
                           +(unsigned)(nt2*32+r)*64+hh*32;
        const uint4* src=(const uint4*)(stg+(r*4+p)*64+hh*32);
#pragma unroll
        for(int i=0;i<4;i++) ((uint4*)dst)[i]=src[i];
    }
    __syncthreads();
    if(wid==0) TC_DEALLOC(tmem,128);
#else
    for(int it=tid;it<4096;it+=256){
        int oL=it>>5,j=it&31,o=mh*128+oL,n=nt2*32+j;
        float acc=0.f;
        for(int kc=0;kc<4;kc++){
            const char* Ai=Ab+(unsigned)(((z*2+mh)*4+kc)*2)*16384u;
            const char* Bi=Bb+(unsigned)(((nt2>>1)*4+kc)*2)*8192u+(unsigned)(nt2&1)*4096u;
            for(int c=0;c<64;c++){
                unsigned ao=SWZ((unsigned)(oL*128+c*2)),bo2=SWZ((unsigned)(j*128+c*2));
                float a=__bfloat162float(*(const __nv_bfloat16*)(Ai+ao))
                       +__bfloat162float(*(const __nv_bfloat16*)(Ai+16384+ao));
                float bvv=__bfloat162float(*(const __nv_bfloat16*)(Bi+bo2))
                         +__bfloat162float(*(const __nv_bfloat16*)(Bi+8192+bo2));
                acc+=a*bvv;
            }
        }
        float val=acc+bb[o];
        if(z==2) g_vh[o*NDIM+n]=__float2half(val);
        else{
            const float CQ=0.17677669529663687f*1.4426950408889634f;
            float vv=val*((z==0)?CQ:1.f);
            __nv_bfloat16 hi=__float2bfloat16(vv);
            __nv_bfloat16* base=((z==0)?g_qp:g_kp)+(o>>5)*(NDIM*64);
            base[n*64+(o&31)]=hi;
            base[n*64+32+(o&31)]=__float2bfloat16(vv-__bfloat162float(hi));
        }
    }
#endif
}

// ---------------- proj GEMM: bulk A + thread-built B, single commit ----------------
__global__ void __launch_bounds__(256,1)
tc_proj(const char* __restrict__ Ab,const float* __restrict__ bp,
        float* __restrict__ outp){
    const int mh=blockIdx.y,ntp=blockIdx.x,tid=threadIdx.x;
#ifdef HAS_TC
    extern __shared__ char sm[];
    const unsigned smb=su32(sm);
    const int wid=tid>>5,lid=tid&31;
    if(wid==0){ TC_ALLOC(smb+163840,128); TC_RELINQ(); }
    if(tid==0){ MBI(smb+163848,1); MBI(smb+163856,1); }
    __syncthreads();
    const char* Abase=Ab+(unsigned)((6+mh)*4*2)*16384u;
    if(tid==0){
        MBX(smb+163848,131072u);
        BULK(smb,Abase,131072u,smb+163848);
    }
    // build B (overlaps bulk A)
    const int nloc=tid>>4,c0=(tid&15)*4;
#pragma unroll
    for(int tt=0;tt<2;tt++){
        const int npo=ntp*32+tt*16+nloc,qt=npo>>7,nl=npo&127;
        const float* pl0=g_po+(unsigned)((qt*8*2+0)*128+nl)*34u;
        const float* pl1=g_po+(unsigned)((qt*8*2+1)*128+nl)*34u;
#pragma unroll
        for(int kc=0;kc<4;kc++){
            int gc=kc*64+c0,Hh=gc>>5,d0=gc&31;
            const float* p0=pl0+(unsigned)(Hh*2)*128u*34u;
            const float* p1=pl1+(unsigned)(Hh*2)*128u*34u;
            float inv=rcpf(p0[32]+p1[32]);
            char* dst=sm+131072+tt*16384+kc*4096;
#pragma unroll
            for(int i=0;i<4;i++){
                float v=(p0[d0+i]+p1[d0+i])*inv;
                __nv_bfloat16 hi=__float2bfloat16(v);
                unsigned off=SWZ((unsigned)(nloc*128+(c0+i)*2));
                *(__nv_bfloat16*)(dst+off)=hi;
                *(__nv_bfloat16*)(dst+2048+off)=__float2bfloat16(v-__bfloat162float(hi));
            }
        }
    }
    FPA(); __syncthreads();
    unsigned tmem; asm volatile("ld.shared.b32 %0,[%1];":"=r"(tmem):"r"(smb+163840));
    MBW(smb+163848,0);
    if(tid==0){
#pragma unroll
        for(int tt=0;tt<2;tt++){
            unsigned dD=tmem+tt*16;
#pragma unroll
            for(int kc=0;kc<4;kc++){
                unsigned long long ah=mkd(smb+kc*32768),al=ah+1024;
                unsigned long long bh=mkd(smb+131072+tt*16384+kc*4096),bl=bh+128;
#pragma unroll
                for(int ks=0;ks<4;ks++){
                    unsigned long long o2=ks*2;
                    mma_ss(dD,ah+o2,bh+o2,IDS16,(kc|ks)!=0);
                    mma_ss(dD,ah+o2,bl+o2,IDS16,1);
                    mma_ss(dD,al+o2,bh+o2,IDS16,1);
                }
            }
        }
        TC_COMMIT(smb+163856);
    }
    MBW(smb+163856,0);
    TC_FA();
    const int sp=wid&3,hf=wid>>2;
    if(hf==0){
        unsigned sr[32];
        TC_LD32(sr,tmem+((unsigned)sp<<21)); TC_WLD();
        const int o=mh*128+sp*32+lid;
        const float bv=bp[o];
#pragma unroll
        for(int j=0;j<32;j++) outp[o*NDIM+ntp*32+j]=__uint_as_float(sr[j])+bv;
    }
    __syncthreads();
    if(wid==0) TC_DEALLOC(tmem,128);
#else
    for(int it=tid;it<4096;it+=256){
        int oL=it>>5,j=it&31,o=mh*128+oL,n=ntp*32+j;
        float acc=0.f;
        for(int kc=0;kc<4;kc++){
            const char* Ai=Ab+(unsigned)(((6+mh)*4+kc)*2)*16384u;
            for(int c=0;c<64;c++){
                unsigned ao=SWZ((unsigned)(oL*128+c*2));
                float a=__bfloat162float(*(const __nv_bfloat16*)(Ai+ao))
                       +__bfloat162float(*(const __nv_bfloat16*)(Ai+16384+ao));
                int qt2=n>>7,nl2=n&127,cg2=kc*64+c,Hh=cg2>>5,d=cg2&31;
                const float* p0=g_po+(unsigned)(((qt2*8+Hh)*2+0)*128+nl2)*34u;
                const float* p1=g_po+(unsigned)(((qt2*8+Hh)*2+1)*128+nl2)*34u;
                acc+=a*(p0[d]+p1[d])/(p0[32]+p1[32]);
            }
        }
        outp[o*NDIM+n]=acc+bp[o];
    }
#endif
}

// ---------------- attention: split-KV + pipelined S (unchanged) ----------------
#define SM_B 64
#define SM_Q 36864
#define SM_K 53248
#define SM_V 77824
#define SM_TOT 98304
#define TPC 18

#ifdef HAS_TC
__device__ __forceinline__ void issue_s(unsigned tmem,unsigned smb,int t){
    unsigned long long kd=mkd(smb+SM_K+(t%3)*8192);
    unsigned long long qd=mkd(smb+SM_Q);
    unsigned tS=tmem+64+(t&1)*64;
    mma_ss(tS,qd+0,kd+0,IDS,0); mma_ss(tS,qd+2,kd+2,IDS,1);
    mma_ss(tS,qd+0,kd+4,IDS,1); mma_ss(tS,qd+2,kd+6,IDS,1);
    mma_ss(tS,qd+4,kd+0,IDS,1); mma_ss(tS,qd+6,kd+2,IDS,1);
    TC_COMMIT(smb+8+8*(t&1));
}
#endif

__global__ void __launch_bounds__(256,2)
attn_kernel(const float* __restrict__ emb){
    extern __shared__ char sm[];
#ifdef HAS_TC
    const unsigned smb=su32(sm);
    const int tid=threadIdx.x,wid=tid>>5,lid=tid&31;
    const int H=blockIdx.y,n0=blockIdx.x*128,half=blockIdx.z;
    const int tbase=half*TPC;
    float* bias=(float*)(sm+SM_B);
    if(wid==0){ TC_ALLOC(smb,256); TC_RELINQ(); }
    if(tid==0){MBI(smb+8,1);MBI(smb+16,1);MBI(smb+24,1);MBI(smb+32,1);}
    for(int i=tid;i<9025;i+=256){
        int a=i/95,b=i-a*95,dx=a-47,dy=b-47;
        if(dx<0)dx=-dx; if(dy<0)dy=-dy;
        bias[i]=(dx<=5&&dy<=5)?emb[(dx*6+dy)*8+H]*1.4426950408889634f:0.f;
    }
    const __nv_bfloat16* qp=g_qp+H*(NDIM*64);
    const __nv_bfloat16* kp=g_kp+H*(NDIM*64);
#pragma unroll
    for(int e=0;e<4;e++){
        int idx=tid+e*256,r=idx>>3,c=(idx&7)*16;
        uint4 v=*(const uint4*)((const char*)(qp+(n0+r)*64)+c);
        *(uint4*)(sm+SM_Q+SWZ(r*128+c))=v;
    }
    {
        int b=tid>>6,i=tid&63,d=32+(i>>3),c=(i&7)*16;
        unsigned w=(d==32)?0x3C003C00u:0u;
        *(uint4*)(sm+SM_V+b*5120+SWZ(d*128+c))=make_uint4(w,w,w,w);
    }
    const int lj=tid>>3, lc=(tid&7)*16, ld=tid>>3;
#pragma unroll
    for(int t=0;t<2;t++){
        int m0=(tbase+t)*64;
        uint4 k0=*(const uint4*)((const char*)(kp+(m0+lj)*64)+lc);
        uint4 k1=*(const uint4*)((const char*)(kp+(m0+lj+32)*64)+lc);
        uint4 vv=*(const uint4*)((const char*)(g_vh+(H*32+ld)*NDIM+m0)+lc);
        *(uint4*)(sm+SM_K+t*8192+SWZ(lj*128+lc))=k0;
        *(uint4*)(sm+SM_K+t*8192+SWZ((lj+32)*128+lc))=k1;
        *(uint4*)(sm+SM_V+t*5120+SWZ(ld*128+lc))=vv;
    }
    FPA(); __syncthreads();
    unsigned tmem; asm volatile("ld.shared.b32 %0,[%1];":"=r"(tmem):"r"(smb));
    if(tid==0) issue_s(tmem,smb,0);
    const int sp=wid&3,hf=wid>>2;
    const unsigned spoff=(unsigned)sp<<21;
    const int n=n0+sp*32+lid,xn=n/48,yn=n-xn*48;
    const float* bp=bias+xn*95+yn+4512;

    for(int t=0;t<TPC;t++){
        if(t<TPC-1&&tid==0) issue_s(tmem,smb,t+1);
        uint4 k0,k1,vv; const bool pf=(t<TPC-2);
        if(pf){
            int m0=(tbase+t+2)*64;
            k0=*(const uint4*)((const char*)(kp+(m0+lj)*64)+lc);
            k1=*(const uint4*)((const char*)(kp+(m0+lj+32)*64)+lc);
            vv=*(const uint4*)((const char*)(g_vh+(H*32+ld)*NDIM+m0)+lc);
        }
        if(t>=2) MBW(smb+24+8*(t&1),((t-2)>>1)&1);
        MBW(smb+8+8*(t&1),(t>>1)&1); TC_FA();
        unsigned sr[32];
        TC_LD32(sr,tmem+64+(t&1)*64+hf*32+spoff); TC_WLD();
        const int mc=(tbase+t)*64+hf*32;
        unsigned pk[16];
#pragma unroll
        for(int jj=0;jj<16;jj++){
            int m0_=mc+2*jj,m1_=m0_+1;
            int x0=(m0_*2731)>>17,x1=(m1_*2731)>>17;
            float p0=ex2f(__uint_as_float(sr[2*jj])+bp[-(m0_+47*x0)]);
            float p1=ex2f(__uint_as_float(sr[2*jj+1])+bp[-(m1_+47*x1)]);
            pk[jj]=f16p(p0,p1);
        }
        const unsigned pbase=tmem+192+(t&1)*32;
        TC_ST16(pbase+hf*16+spoff,pk); TC_WST();
        if(pf){
            int ko=SM_K+((t+2)%3)*8192, vo=SM_V+((t+2)%4)*5120;
            *(uint4*)(sm+ko+SWZ(lj*128+lc))=k0;
            *(uint4*)(sm+ko+SWZ((lj+32)*128+lc))=k1;
            *(uint4*)(sm+vo+SWZ(ld*128+lc))=vv;
        }
        TC_FB(); FPA(); __syncthreads();
        if(tid==0){
            TC_FA();
            unsigned long long vd=mkd(smb+SM_V+(t%4)*5120);
#pragma unroll
            for(int k=0;k<4;k++) mma_ts(tmem,pbase+k*8,vd+k*2,IDP,(t+k)>0);
            TC_COMMIT(smb+24+8*(t&1));
        }
    }
    MBW(smb+24,0); MBW(smb+32,0);
    TC_FA();
    if(hf==0){
        unsigned od[32],lr;
        TC_LD32(od,tmem+spoff); TC_LD1(lr,tmem+32+spoff); TC_WLD();
        float* po=g_po+(unsigned)(((blockIdx.x*8+H)*2+half)*128+sp*32+lid)*34u;
#pragma unroll
        for(int d=0;d<32;d++) po[d]=__uint_as_float(od[d]);
        po[32]=__uint_as_float(lr);
    }
    __syncthreads();
    if(wid==0) TC_DEALLOC(tmem,256);
#else
    const int tid=threadIdx.x,H=blockIdx.y,n0=blockIdx.x*128,half=blockIdx.z;
    if(tid<128){
        int n=n0+tid,xn=n/48,yn=n-48*xn;
        const __nv_bfloat16* qr=g_qp+H*(NDIM*64)+n*64;
        float qv[32],o[32],l=0.f;
#pragma unroll
        for(int d=0;d<32;d++){qv[d]=__bfloat162float(qr[d])+__bfloat162float(qr[32+d]);o[d]=0.f;}
        for(int mt=0;mt<TPC*64;mt++){
            int m=half*TPC*64+mt;
            const __nv_bfloat16* kr=g_kp+H*(NDIM*64)+m*64;
            float s=0.f;
            for(int d=0;d<32;d++) s+=qv[d]*(__bfloat162float(kr[d])+__bfloat162float(kr[32+d]));
            int xm=m/48,ym=m-48*xm,dx=xn-xm,dy=yn-ym;
            if(dx<0)dx=-dx; if(dy<0)dy=-dy;
            float b=(dx<6&&dy<6)?emb[(dx*6+dy)*8+H]*1.4426950408889634f:0.f;
            float p=exp2f(s+b); l+=p;
            for(int d=0;d<32;d++) o[d]+=p*__half2float(g_vh[(H*32+d)*NDIM+m]);
        }
        float* po=g_po+(unsigned)(((blockIdx.x*8+H)*2+half)*128+tid)*34u;
        for(int d=0;d<32;d++) po[d]=o[d];
        po[32]=l;
    }
#endif
}

extern "C" void kernel_launch(void* const* d_in,const int* in_sizes,int n_in,
                              void* d_out,int out_size){
    const float* x  =(const float*)d_in[0];
    const float* Wq =(const float*)d_in[1]; const float* bq=(const float*)d_in[2];
    const float* Wk =(const float*)d_in[3]; const float* bk=(const float*)d_in[4];
    const float* Wv =(const float*)d_in[5]; const float* bv=(const float*)d_in[6];
    const float* Wp =(const float*)d_in[7]; const float* bp=(const float*)d_in[8];
    const float* emb=(const float*)d_in[9];
    float* out=(float*)d_out;
    char* wsp; char* xt;
    cudaGetSymbolAddress((void**)&wsp,g_wsp);
    cudaGetSymbolAddress((void**)&xt,g_xt);
    cudaFuncSetAttribute(tc_gemm,cudaFuncAttributeMaxDynamicSharedMemorySize,GM2);
    cudaFuncSetAttribute(tc_proj,cudaFuncAttributeMaxDynamicSharedMemorySize,GM2);
    cudaFuncSetAttribute(attn_kernel,cudaFuncAttributeMaxDynamicSharedMemorySize,SM_TOT);
    prep_all<<<176,256>>>(x,Wq,Wk,Wv,Wp);
    tc_gemm<<<dim3(72,2,3),256,GM2>>>(wsp,xt,bq,bk,bv);
    attn_kernel<<<dim3(18,HEADS,2),256,SM_TOT>>>(emb);
    tc_proj<<<dim3(72,2),256,GM2>>>(wsp,bp,out);
}

// round 16
// speedup vs baseline: 1.1217x; 1.0669x over previous
#include <cuda_runtime.h>
#include <cuda_bf16.h>
#include <cuda_fp16.h>
#define NDIM 2304
#define HEADS 8

__device__ __align__(16) char g_wsp[4*2*4*2*16384];
__device__ __align__(16) char g_xt [4*2*294912];   // [kc][half] contiguous planes
__device__ __align__(16) __nv_bfloat16 g_qp[HEADS*NDIM*64];
__device__ __align__(16) __nv_bfloat16 g_kp[HEADS*NDIM*64];
__device__ __align__(16) __half g_vh[256*NDIM];
__device__ __align__(16) float g_po[18*8*2*128*34];

#if defined(__CUDA_ARCH_FEAT_SM103_ALL) || defined(__CUDA_ARCH_FEAT_SM100_ALL)
#define HAS_TC 1
#endif

__device__ __forceinline__ unsigned su32(const void*p){unsigned a;
    asm("{.reg .u64 t; cvta.to.shared.u64 t,%1; cvt.u32.u64 %0,t;}":"=r"(a):"l"(p));return a;}
#define TC_ALLOC(sa,n) asm volatile("tcgen05.alloc.cta_group::1.sync.aligned.shared::cta.b32 [%0],%1;"::"r"(sa),"r"(n):"memory")
#define TC_RELINQ() asm volatile("tcgen05.relinquish_alloc_permit.cta_group::1.sync.aligned;")
#define TC_DEALLOC(t,n) asm volatile("tcgen05.dealloc.cta_group::1.sync.aligned.b32 %0,%1;"::"r"(t),"r"(n))
#define TC_COMMIT(mb) asm volatile("tcgen05.commit.cta_group::1.mbarrier::arrive::one.shared::cluster.b64 [%0];"::"r"(mb):"memory")
#define TC_FA() asm volatile("tcgen05.fence::after_thread_sync;":::"memory")
#define TC_FB() asm volatile("tcgen05.fence::before_thread_sync;":::"memory")
#define TC_WLD() asm volatile("tcgen05.wait::ld.sync.aligned;":::"memory")
#define TC_WST() asm volatile("tcgen05.wait::st.sync.aligned;":::"memory")
#define FPA() asm volatile("fence.proxy.async.shared::cta;":::"memory")
#define MBI(mb,c) asm volatile("mbarrier.init.shared.b64 [%0],%1;"::"r"(mb),"r"(c):"memory")
#define MBW(mb,ph) do{unsigned _d=0;while(!_d){asm volatile("{.reg .pred p;\n mbarrier.try_wait.parity.acquire.cta.shared::cta.b64 p,[%1],%2;\n selp.b32 %0,1,0,p;}":"=r"(_d):"r"(mb),"r"(ph):"memory");}}while(0)
#define TC_LD32(r,a) asm volatile("tcgen05.ld.sync.aligned.32x32b.x32.b32 {%0,%1,%2,%3,%4,%5,%6,%7,%8,%9,%10,%11,%12,%13,%14,%15,%16,%17,%18,%19,%20,%21,%22,%23,%24,%25,%26,%27,%28,%29,%30,%31},[%32];" \
 :"=r"((r)[0]),"=r"((r)[1]),"=r"((r)[2]),"=r"((r)[3]),"=r"((r)[4]),"=r"((r)[5]),"=r"((r)[6]),"=r"((r)[7]),"=r"((r)[8]),"=r"((r)[9]),"=r"((r)[10]),"=r"((r)[11]),"=r"((r)[12]),"=r"((r)[13]),"=r"((r)[14]),"=r"((r)[15]), \
  "=r"((r)[16]),"=r"((r)[17]),"=r"((r)[18]),"=r"((r)[19]),"=r"((r)[20]),"=r"((r)[21]),"=r"((r)[22]),"=r"((r)[23]),"=r"((r)[24]),"=r"((r)[25]),"=r"((r)[26]),"=r"((r)[27]),"=r"((r)[28]),"=r"((r)[29]),"=r"((r)[30]),"=r"((r)[31]):"r"(a))
#define TC_LD16(r,a) asm volatile("tcgen05.ld.sync.aligned.32x32b.x16.b32 {%0,%1,%2,%3,%4,%5,%6,%7,%8,%9,%10,%11,%12,%13,%14,%15},[%16];" \
 :"=r"((r)[0]),"=r"((r)[1]),"=r"((r)[2]),"=r"((r)[3]),"=r"((r)[4]),"=r"((r)[5]),"=r"((r)[6]),"=r"((r)[7]), \
  "=r"((r)[8]),"=r"((r)[9]),"=r"((r)[10]),"=r"((r)[11]),"=r"((r)[12]),"=r"((r)[13]),"=r"((r)[14]),"=r"((r)[15]):"r"(a))
#define TC_LD1(r0,a) asm volatile("tcgen05.ld.sync.aligned.32x32b.x1.b32 {%0},[%1];":"=r"(r0):"r"(a))
#define TC_ST16(a,r) asm volatile("tcgen05.st.sync.aligned.32x32b.x16.b32 [%0],{%1,%2,%3,%4,%5,%6,%7,%8,%9,%10,%11,%12,%13,%14,%15,%16};" \
 ::"r"(a),"r"((r)[0]),"r"((r)[1]),"r"((r)[2]),"r"((r)[3]),"r"((r)[4]),"r"((r)[5]),"r"((r)[6]),"r"((r)[7]),"r"((r)[8]),"r"((r)[9]),"r"((r)[10]),"r"((r)[11]),"r"((r)[12]),"r"((r)[13]),"r"((r)[14]),"r"((r)[15]):"memory")
#define SWZ(x) ((x)^(((x)>>3)&0x70))
__device__ __forceinline__ unsigned long long mkd(unsigned a){
    return ((2ull<<61)|(1ull<<46)|(64ull<<32)|(1ull<<16))|((unsigned long long)(a>>4)&0x3FFF);}
__device__ __forceinline__ void mma_ss(unsigned d,unsigned long long a,unsigned long long b,unsigned id,unsigned en){
    asm volatile("{.reg .pred p;\n setp.ne.u32 p,%5,0;\n tcgen05.mma.cta_group::1.kind::f16 [%0],%1,%2,%3,{%4,%4,%4,%4},p;}"
    ::"r"(d),"l"(a),"l"(b),"r"(id),"r"(0u),"r"(en):"memory");}
__device__ __forceinline__ void mma_ts(unsigned d,unsigned a,unsigned long long b,unsigned id,unsigned en){
    asm volatile("{.reg .pred p;\n setp.ne.u32 p,%5,0;\n tcgen05.mma.cta_group::1.kind::f16 [%0],[%1],%2,%3,{%4,%4,%4,%4},p;}"
    ::"r"(d),"r"(a),"l"(b),"r"(id),"r"(0u),"r"(en):"memory");}
__device__ __forceinline__ float ex2f(float x){float y;asm("ex2.approx.ftz.f32 %0,%1;":"=f"(y):"f"(x));return y;}
__device__ __forceinline__ float rcpf(float x){float y;asm("rcp.approx.ftz.f32 %0,%1;":"=f"(y):"f"(x));return y;}
__device__ __forceinline__ unsigned f16p(float lo,float hi){unsigned r;
    asm("cvt.rn.f16x2.f32 %0,%1,%2;":"=r"(r):"f"(hi),"f"(lo));return r;}
#define IDS 0x8100490u
#define IDS48 0x80C0490u
#define IDS16 0x8040490u
#define IDP 0x80A0010u
#define XPL 294912u

// ---------------- prep (merged W + X; X -> contiguous planes) ----------------
__global__ void __launch_bounds__(256)
prep_all(const float* __restrict__ x,const float* __restrict__ Wq,
         const float* __restrict__ Wk,const float* __restrict__ Wv,
         const float* __restrict__ Wp){
    const int b=blockIdx.x,tid=threadIdx.x;
    if(b<32){
        const int z=b>>3,mh=(b>>2)&1,kc=b&3;
        const float* W=(z==0)?Wq:(z==1)?Wk:(z==2)?Wv:Wp;
        char* img=g_wsp+(unsigned)(((z*2+mh)*4+kc)*2)*16384u;
        int r=tid>>1,c0=(tid&1)*32;
#pragma unroll
        for(int cc=0;cc<32;cc++){
            int c=c0+cc;
            float v=W[(mh*128+r)*256+kc*64+c];
            __nv_bfloat16 hi=__float2bfloat16(v);
            unsigned off=SWZ((unsigned)(r*128+c*2));
            *(__nv_bfloat16*)(img+off)=hi;
            *(__nv_bfloat16*)(img+16384+off)=__float2bfloat16(v-__bfloat162float(hi));
        }
    }else{
        const int q=b-32,nt=q>>2,kc=q&3;
        char* hip=g_xt+(unsigned)(kc*2)*XPL;
        char* lop=hip+XPL;
        int c=tid>>2,r0=(tid&3)*16;
#pragma unroll
        for(int rr=0;rr<16;rr++){
            int g=nt*64+r0+rr;
            float v=x[(kc*64+c)*NDIM+g];
            __nv_bfloat16 hi=__float2bfloat16(v);
            unsigned off=SWZ((unsigned)(g*128+c*2));
            *(__nv_bfloat16*)(hip+off)=hi;
            *(__nv_bfloat16*)(lop+off)=__float2bfloat16(v-__bfloat162float(hi));
        }
    }
}

// ---------------- QKV GEMM: 128o x 48n tiles, chunked reg-prefetch pipeline ----------------
#define CHS 45056
#define GM_SZ 90176
__global__ void __launch_bounds__(256,2)
tc_gemm(const char* __restrict__ Ab,const char* __restrict__ Bb,
        const float* __restrict__ b0,const float* __restrict__ b1,
        const float* __restrict__ b2){
    const int z=blockIdx.z,mh=blockIdx.y,nt=blockIdx.x,tid=threadIdx.x;
    const float* bb=(z==0)?b0:(z==1)?b1:b2;
#ifdef HAS_TC
    extern __shared__ char sm[];
    const unsigned smb=su32(sm);
    const int wid=tid>>5,lid=tid&31;
    if(wid==0){ TC_ALLOC(smb+90112,128); TC_RELINQ(); }
    if(tid==0){ MBI(smb+90120,1); MBI(smb+90128,1); }
    const char* Abase=Ab+(unsigned)((z*2+mh)*4*2)*16384u;
    // chunk 0
#pragma unroll
    for(int i=0;i<8;i++) *(uint4*)(sm+tid*16+i*4096)=*(const uint4*)(Abase+tid*16+i*4096);
    {
        const char* hip=Bb+(unsigned)nt*6144u;
#pragma unroll
        for(int i=0;i<3;i++){
            unsigned off=tid*16+i*4096;
            const char* src=(off<6144u)?(hip+off):(hip+XPL+off-6144u);
            *(uint4*)(sm+32768+off)=*(const uint4*)src;
        }
    }
    FPA(); __syncthreads();
    unsigned tmem; asm volatile("ld.shared.b32 %0,[%1];":"=r"(tmem):"r"(smb+90112));
#pragma unroll
    for(int kc=0;kc<4;kc++){
        const unsigned bo=(kc&1)*CHS;
        if(tid==0){
            unsigned long long ah=mkd(smb+bo),al=ah+1024;
            unsigned long long bh=mkd(smb+bo+32768),bl=bh+384;
#pragma unroll
            for(int ks=0;ks<4;ks++){
                unsigned long long o2=ks*2;
                mma_ss(tmem,ah+o2,bh+o2,IDS48,(kc|ks)!=0);
                mma_ss(tmem,ah+o2,bl+o2,IDS48,1);
                mma_ss(tmem,al+o2,bh+o2,IDS48,1);
            }
            TC_COMMIT(smb+90120+8*(kc&1));
        }
        if(kc<3){
            uint4 ar[8],br[3];
            const char* An=Abase+(unsigned)(kc+1)*32768u;
#pragma unroll
            for(int i=0;i<8;i++) ar[i]=*(const uint4*)(An+tid*16+i*4096);
            const char* hip=Bb+(unsigned)(kc+1)*2*XPL+(unsigned)nt*6144u;
#pragma unroll
            for(int i=0;i<3;i++){
                unsigned off=tid*16+i*4096;
                br[i]=*(const uint4*)((off<6144u)?(hip+off):(hip+XPL+off-6144u));
            }
            if(kc>=1) MBW(smb+90120+8*((kc-1)&1),((kc-1)>>1)&1);
            const unsigned nb=((kc+1)&1)*CHS;
#pragma unroll
            for(int i=0;i<8;i++) *(uint4*)(sm+nb+tid*16+i*4096)=ar[i];
#pragma unroll
            for(int i=0;i<3;i++) *(uint4*)(sm+nb+32768+tid*16+i*4096)=br[i];
            FPA(); __syncthreads();
        }
    }
    MBW(smb+90128,1);
    TC_FA();
    const int sp=wid&3,hf=wid>>2;
    if(hf==0){
        unsigned sr[48];
        TC_LD32(sr,tmem+((unsigned)sp<<21));
        TC_LD16(sr+32,tmem+32+((unsigned)sp<<21));
        TC_WLD();
        const int o=mh*128+sp*32+lid;
        const float bv=bb[o];
        if(z==2){
            unsigned hw[24];
#pragma unroll
            for(int jj=0;jj<24;jj++)
                hw[jj]=f16p(__uint_as_float(sr[2*jj])+bv,__uint_as_float(sr[2*jj+1])+bv);
            uint4* dst=(uint4*)(g_vh+(unsigned)o*NDIM+nt*48);
#pragma unroll
            for(int i=0;i<6;i++) dst[i]=make_uint4(hw[4*i],hw[4*i+1],hw[4*i+2],hw[4*i+3]);
        }else{
            const float CQ=0.17677669529663687f*1.4426950408889634f;
            const float cm=(z==0)?CQ:1.f;
            __nv_bfloat16* stg=(__nv_bfloat16*)sm;
#pragma unroll
            for(int j=0;j<48;j++){
                float vv=(__uint_as_float(sr[j])+bv)*cm;
                __nv_bfloat16 hi=__float2bfloat16(vv);
                stg[(j*4+sp)*64+lid]=hi;
                stg[(j*4+sp)*64+32+lid]=__float2bfloat16(vv-__bfloat162float(hi));
            }
        }
    }
    __syncthreads();
    if(z<2){
        const __nv_bfloat16* stg=(const __nv_bfloat16*)sm;
#pragma unroll
        for(int e=0;e<2;e++){
            int idx=tid+e*256;
            if(idx<384){
                int r=idx>>3,p=(idx&7)>>1,hh=idx&1;
                __nv_bfloat16* dst=((z==0)?g_qp:g_kp)+(unsigned)(mh*4+p)*(NDIM*64)
                                   +(unsigned)(nt*48+r)*64+hh*32;
                const uint4* src=(const uint4*)(stg+(r*4+p)*64+hh*32);
#pragma unroll
                for(int i=0;i<4;i++) ((uint4*)dst)[i]=src[i];
            }
        }
    }
    __syncthreads();
    if(wid==0) TC_DEALLOC(tmem,128);
#else
    for(int it=tid;it<6144;it+=256){
        int oL=it/48,j=it%48,o=mh*128+oL,n=nt*48+j;
        float acc=0.f;
        for(int kc=0;kc<4;kc++){
            const char* Ai=Ab+(unsigned)(((z*2+mh)*4+kc)*2)*16384u;
            const char* hip=Bb+(unsigned)(kc*2)*XPL;
            for(int c=0;c<64;c++){
                unsigned ao=SWZ((unsigned)(oL*128+c*2)),bo2=SWZ((unsigned)(n*128+c*2));
                float a=__bfloat162float(*(const __nv_bfloat16*)(Ai+ao))
                       +__bfloat162float(*(const __nv_bfloat16*)(Ai+16384+ao));
                float bvv=__bfloat162float(*(const __nv_bfloat16*)(hip+bo2))
                         +__bfloat162float(*(const __nv_bfloat16*)(hip+XPL+bo2));
                acc+=a*bvv;
            }
        }
        float val=acc+bb[o];
        if(z==2) g_vh[o*NDIM+n]=__float2half(val);
        else{
            const float CQ=0.17677669529663687f*1.4426950408889634f;
            float vv=val*((z==0)?CQ:1.f);
            __nv_bfloat16 hi=__float2bfloat16(vv);
            __nv_bfloat16* base=((z==0)?g_qp:g_kp)+(o>>5)*(NDIM*64);
            base[n*64+(o&31)]=hi;
            base[n*64+32+(o&31)]=__float2bfloat16(vv-__bfloat162float(hi));
        }
    }
#endif
}

// ---------------- proj GEMM: 128o x 16n tiles, chunked, B from partials (R13) ----------------
#define PCHS 40960
#define PM_SZ 81984
__global__ void __launch_bounds__(256,2)
tc_proj(const char* __restrict__ Ab,const float* __restrict__ bp,
        float* __restrict__ outp){
    const int mh=blockIdx.y,nt4=blockIdx.x,tid=threadIdx.x;
#ifdef HAS_TC
    extern __shared__ char sm[];
    const unsigned smb=su32(sm);
    const int wid=tid>>5,lid=tid&31;
    if(wid==0){ TC_ALLOC(smb+81920,128); TC_RELINQ(); }
    if(tid==0){ MBI(smb+81928,1); MBI(smb+81936,1); }
    const char* Abase=Ab+(unsigned)((6+mh)*4*2)*16384u;
    const int nloc=tid>>4,c0=(tid&15)*4;
    const int npo=nt4*16+nloc,qt=npo>>7,nl=npo&127;
#pragma unroll
    for(int i=0;i<8;i++) *(uint4*)(sm+tid*16+i*4096)=*(const uint4*)(Abase+tid*16+i*4096);
    {
        int gc=c0,Hh=gc>>5,d0=gc&31;
        const float* p0=g_po+(unsigned)(((qt*8+Hh)*2+0)*128+nl)*34u;
        const float* p1=g_po+(unsigned)(((qt*8+Hh)*2+1)*128+nl)*34u;
        float inv=rcpf(p0[32]+p1[32]);
#pragma unroll
        for(int i=0;i<4;i++){
            float v=(p0[d0+i]+p1[d0+i])*inv;
            __nv_bfloat16 hi=__float2bfloat16(v);
            unsigned off=SWZ((unsigned)(nloc*128+(c0+i)*2));
            *(__nv_bfloat16*)(sm+32768+off)=hi;
            *(__nv_bfloat16*)(sm+32768+2048+off)=__float2bfloat16(v-__bfloat162float(hi));
        }
    }
    FPA(); __syncthreads();
    unsigned tmem; asm volatile("ld.shared.b32 %0,[%1];":"=r"(tmem):"r"(smb+81920));
#pragma unroll
    for(int kc=0;kc<4;kc++){
        const unsigned bo=(kc&1)*PCHS;
        if(tid==0){
            unsigned long long ah=mkd(smb+bo),al=ah+1024;
            unsigned long long bh=mkd(smb+bo+32768),bl=bh+128;
#pragma unroll
            for(int ks=0;ks<4;ks++){
                unsigned long long o2=ks*2;
                mma_ss(tmem,ah+o2,bh+o2,IDS16,(kc|ks)!=0);
                mma_ss(tmem,ah+o2,bl+o2,IDS16,1);
                mma_ss(tmem,al+o2,bh+o2,IDS16,1);
            }
            TC_COMMIT(smb+81928+8*(kc&1));
        }
        if(kc<3){
            uint4 ar[8];
            const char* An=Abase+(unsigned)(kc+1)*32768u;
#pragma unroll
            for(int i=0;i<8;i++) ar[i]=*(const uint4*)(An+tid*16+i*4096);
            int gc=(kc+1)*64+c0,Hh=gc>>5,d0=gc&31;
            const float* p0=g_po+(unsigned)(((qt*8+Hh)*2+0)*128+nl)*34u;
            const float* p1=g_po+(unsigned)(((qt*8+Hh)*2+1)*128+nl)*34u;
            float inv=rcpf(p0[32]+p1[32]);
            float pv[4];
#pragma unroll
            for(int i=0;i<4;i++) pv[i]=(p0[d0+i]+p1[d0+i])*inv;
            if(kc>=1) MBW(smb+81928+8*((kc-1)&1),((kc-1)>>1)&1);
            const unsigned nb=((kc+1)&1)*PCHS;
#pragma unroll
            for(int i=0;i<8;i++) *(uint4*)(sm+nb+tid*16+i*4096)=ar[i];
#pragma unroll
            for(int i=0;i<4;i++){
                __nv_bfloat16 hi=__float2bfloat16(pv[i]);
                unsigned off=SWZ((unsigned)(nloc*128+(c0+i)*2));
                *(__nv_bfloat16*)(sm+nb+32768+off)=hi;
                *(__nv_bfloat16*)(sm+nb+32768+2048+off)=__float2bfloat16(pv[i]-__bfloat162float(hi));
            }
            FPA(); __syncthreads();
        }
    }
    MBW(smb+81936,1);
    TC_FA();
    const int sp=wid&3,hf=wid>>2;
    if(hf==0){
        unsigned sr[16];
        TC_LD16(sr,tmem+((unsigned)sp<<21)); TC_WLD();
        const int o=mh*128+sp*32+lid;
        const float bv=bp[o];
#pragma unroll
        for(int j=0;j<16;j++) outp[o*NDIM+nt4*16+j]=__uint_as_float(sr[j])+bv;
    }
    __syncthreads();
    if(wid==0) TC_DEALLOC(tmem,128);
#else
    for(int it=tid;it<2048;it+=256){
        int oL=it>>4,j=it&15,o=mh*128+oL,n=nt4*16+j;
        float acc=0.f;
        for(int kc=0;kc<4;kc++){
            const char* Ai=Ab+(unsigned)(((6+mh)*4+kc)*2)*16384u;
            for(int c=0;c<64;c++){
                unsigned ao=SWZ((unsigned)(oL*128+c*2));
                float a=__bfloat162float(*(const __nv_bfloat16*)(Ai+ao))
                       +__bfloat162float(*(const __nv_bfloat16*)(Ai+16384+ao));
                int qt2=n>>7,nl2=n&127,cg2=kc*64+c,Hh=cg2>>5,d=cg2&31;
                const float* p0=g_po+(unsigned)(((qt2*8+Hh)*2+0)*128+nl2)*34u;
                const float* p1=g_po+(unsigned)(((qt2*8+Hh)*2+1)*128+nl2)*34u;
                acc+=a*(p0[d]+p1[d])/(p0[32]+p1[32]);
            }
        }
        outp[o*NDIM+n]=acc+bp[o];
    }
#endif
}

// ---------------- attention: split-KV + pipelined S (R13, unchanged) ----------------
#define SM_B 64
#define SM_Q 36864
#define SM_K 53248
#define SM_V 77824
#define SM_TOT 98304
#define TPC 18

#ifdef HAS_TC
__device__ __forceinline__ void issue_s(unsigned tmem,unsigned smb,int t){
    unsigned long long kd=mkd(smb+SM_K+(t%3)*8192);
    unsigned long long qd=mkd(smb+SM_Q);
    unsigned tS=tmem+64+(t&1)*64;
    mma_ss(tS,qd+0,kd+0,IDS,0); mma_ss(tS,qd+2,kd+2,IDS,1);
    mma_ss(tS,qd+0,kd+4,IDS,1); mma_ss(tS,qd+2,kd+6,IDS,1);
    mma_ss(tS,qd+4,kd+0,IDS,1); mma_ss(tS,qd+6,kd+2,IDS,1);
    TC_COMMIT(smb+8+8*(t&1));
}
#endif

__global__ void __launch_bounds__(256,2)
attn_kernel(const float* __restrict__ emb){
    extern __shared__ char sm[];
#ifdef HAS_TC
    const unsigned smb=su32(sm);
    const int tid=threadIdx.x,wid=tid>>5,lid=tid&31;
    const int H=blockIdx.y,n0=blockIdx.x*128,half=blockIdx.z;
    const int tbase=half*TPC;
    float* bias=(float*)(sm+SM_B);
    if(wid==0){ TC_ALLOC(smb,256); TC_RELINQ(); }
    if(tid==0){MBI(smb+8,1);MBI(smb+16,1);MBI(smb+24,1);MBI(smb+32,1);}
    for(int i=tid;i<9025;i+=256){
        int a=i/95,b=i-a*95,dx=a-47,dy=b-47;
        if(dx<0)dx=-dx; if(dy<0)dy=-dy;
        bias[i]=(dx<=5&&dy<=5)?emb[(dx*6+dy)*8+H]*1.4426950408889634f:0.f;
    }
    const __nv_bfloat16* qp=g_qp+H*(NDIM*64);
    const __nv_bfloat16* kp=g_kp+H*(NDIM*64);
#pragma unroll
    for(int e=0;e<4;e++){
        int idx=tid+e*256,r=idx>>3,c=(idx&7)*16;
        uint4 v=*(const uint4*)((const char*)(qp+(n0+r)*64)+c);
        *(uint4*)(sm+SM_Q+SWZ(r*128+c))=v;
    }
    {
        int b=tid>>6,i=tid&63,d=32+(i>>3),c=(i&7)*16;
        unsigned w=(d==32)?0x3C003C00u:0u;
        *(uint4*)(sm+SM_V+b*5120+SWZ(d*128+c))=make_uint4(w,w,w,w);
    }
    const int lj=tid>>3, lc=(tid&7)*16, ld=tid>>3;
#pragma unroll
    for(int t=0;t<2;t++){
        int m0=(tbase+t)*64;
        uint4 k0=*(const uint4*)((const char*)(kp+(m0+lj)*64)+lc);
        uint4 k1=*(const uint4*)((const char*)(kp+(m0+lj+32)*64)+lc);
        uint4 vv=*(const uint4*)((const char*)(g_vh+(H*32+ld)*NDIM+m0)+lc);
        *(uint4*)(sm+SM_K+t*8192+SWZ(lj*128+lc))=k0;
        *(uint4*)(sm+SM_K+t*8192+SWZ((lj+32)*128+lc))=k1;
        *(uint4*)(sm+SM_V+t*5120+SWZ(ld*128+lc))=vv;
    }
    FPA(); __syncthreads();
    unsigned tmem; asm volatile("ld.shared.b32 %0,[%1];":"=r"(tmem):"r"(smb));
    if(tid==0) issue_s(tmem,smb,0);
    const int sp=wid&3,hf=wid>>2;
    const unsigned spoff=(unsigned)sp<<21;
    const int n=n0+sp*32+lid,xn=n/48,yn=n-xn*48;
    const float* bp=bias+xn*95+yn+4512;

    for(int t=0;t<TPC;t++){
        if(t<TPC-1&&tid==0) issue_s(tmem,smb,t+1);
        uint4 k0,k1,vv; const bool pf=(t<TPC-2);
        if(pf){
            int m0=(tbase+t+2)*64;
            k0=*(const uint4*)((const char*)(kp+(m0+lj)*64)+lc);
            k1=*(const uint4*)((const char*)(kp+(m0+lj+32)*64)+lc);
            vv=*(const uint4*)((const char*)(g_vh+(H*32+ld)*NDIM+m0)+lc);
        }
        if(t>=2) MBW(smb+24+8*(t&1),((t-2)>>1)&1);
        MBW(smb+8+8*(t&1),(t>>1)&1); TC_FA();
        unsigned sr[32];
        TC_LD32(sr,tmem+64+(t&1)*64+hf*32+spoff); TC_WLD();
        const int mc=(tbase+t)*64+hf*32;
        unsigned pk[16];
#pragma unroll
        for(int jj=0;jj<16;jj++){
            int m0_=mc+2*jj,m1_=m0_+1;
            int x0=(m0_*2731)>>17,x1=(m1_*2731)>>17;
            float p0=ex2f(__uint_as_float(sr[2*jj])+bp[-(m0_+47*x0)]);
            float p1=ex2f(__uint_as_float(sr[2*jj+1])+bp[-(m1_+47*x1)]);
            pk[jj]=f16p(p0,p1);
        }
        const unsigned pbase=tmem+192+(t&1)*32;
        TC_ST16(pbase+hf*16+spoff,pk); TC_WST();
        if(pf){
            int ko=SM_K+((t+2)%3)*8192, vo=SM_V+((t+2)%4)*5120;
            *(uint4*)(sm+ko+SWZ(lj*128+lc))=k0;
            *(uint4*)(sm+ko+SWZ((lj+32)*128+lc))=k1;
            *(uint4*)(sm+vo+SWZ(ld*128+lc))=vv;
        }
        TC_FB(); FPA(); __syncthreads();
        if(tid==0){
            TC_FA();
            unsigned long long vd=mkd(smb+SM_V+(t%4)*5120);
#pragma unroll
            for(int k=0;k<4;k++) mma_ts(tmem,pbase+k*8,vd+k*2,IDP,(t+k)>0);
            TC_COMMIT(smb+24+8*(t&1));
        }
    }
    MBW(smb+24,0); MBW(smb+32,0);
    TC_FA();
    if(hf==0){
        unsigned od[32],lr;
        TC_LD32(od,tmem+spoff); TC_LD1(lr,tmem+32+spoff); TC_WLD();
        float* po=g_po+(unsigned)(((blockIdx.x*8+H)*2+half)*128+sp*32+lid)*34u;
#pragma unroll
        for(int d=0;d<32;d++) po[d]=__uint_as_float(od[d]);
        po[32]=__uint_as_float(lr);
    }
    __syncthreads();
    if(wid==0) TC_DEALLOC(tmem,256);
#else
    const int tid=threadIdx.x,H=blockIdx.y,n0=blockIdx.x*128,half=blockIdx.z;
    if(tid<128){
        int n=n0+tid,xn=n/48,yn=n-48*xn;
        const __nv_bfloat16* qr=g_qp+H*(NDIM*64)+n*64;
        float qv[32],o[32],l=0.f;
#pragma unroll
        for(int d=0;d<32;d++){qv[d]=__bfloat162float(qr[d])+__bfloat162float(qr[32+d]);o[d]=0.f;}
        for(int mt=0;mt<TPC*64;mt++){
            int m=half*TPC*64+mt;
            const __nv_bfloat16* kr=g_kp+H*(NDIM*64)+m*64;
            float s=0.f;
            for(int d=0;d<32;d++) s+=qv[d]*(__bfloat162float(kr[d])+__bfloat162float(kr[32+d]));
            int xm=m/48,ym=m-48*xm,dx=xn-xm,dy=yn-ym;
            if(dx<0)dx=-dx; if(dy<0)dy=-dy;
            float b=(dx<6&&dy<6)?emb[(dx*6+dy)*8+H]*1.4426950408889634f:0.f;
            float p=exp2f(s+b); l+=p;
            for(int d=0;d<32;d++) o[d]+=p*__half2float(g_vh[(H*32+d)*NDIM+m]);
        }
        float* po=g_po+(unsigned)(((blockIdx.x*8+H)*2+half)*128+tid)*34u;
        for(int d=0;d<32;d++) po[d]=o[d];
        po[32]=l;
    }
#endif
}

extern "C" void kernel_launch(void* const* d_in,const int* in_sizes,int n_in,
                              void* d_out,int out_size){
    const float* x  =(const float*)d_in[0];
    const float* Wq =(const float*)d_in[1]; const float* bq=(const float*)d_in[2];
    const float* Wk =(const float*)d_in[3]; const float* bk=(const float*)d_in[4];
    const float* Wv =(const float*)d_in[5]; const float* bv=(const float*)d_in[6];
    const float* Wp =(const float*)d_in[7]; const float* bp=(const float*)d_in[8];
    const float* emb=(const float*)d_in[9];
    float* out=(float*)d_out;
    char* wsp; char* xt;
    cudaGetSymbolAddress((void**)&wsp,g_wsp);
    cudaGetSymbolAddress((void**)&xt,g_xt);
    cudaFuncSetAttribute(tc_gemm,cudaFuncAttributeMaxDynamicSharedMemorySize,GM_SZ);
    cudaFuncSetAttribute(tc_proj,cudaFuncAttributeMaxDynamicSharedMemorySize,PM_SZ);
    cudaFuncSetAttribute(attn_kernel,cudaFuncAttributeMaxDynamicSharedMemorySize,SM_TOT);
    prep_all<<<176,256>>>(x,Wq,Wk,Wv,Wp);
    tc_gemm<<<dim3(48,2,3),256,GM_SZ>>>(wsp,xt,bq,bk,bv);
    attn_kernel<<<dim3(18,HEADS,2),256,SM_TOT>>>(emb);
    tc_proj<<<dim3(144,2),256,PM_SZ>>>(wsp,bp,out);
}

// round 17
// speedup vs baseline: 1.4905x; 1.3288x over previous
#include <cuda_runtime.h>
#include <cuda_bf16.h>
#include <cuda_fp16.h>
#define NDIM 2304
#define HEADS 8

__device__ __align__(16) char g_wsp[4*2*4*2*16384];
__device__ __align__(16) char g_xt [4*2*294912];   // [kc][half] contiguous planes
__device__ __align__(16) __nv_bfloat16 g_qp[HEADS*NDIM*64];
__device__ __align__(16) __nv_bfloat16 g_kp[HEADS*NDIM*64];
__device__ __align__(16) __half g_vh[256*NDIM];
__device__ __align__(16) float g_po[18*8*2*128*36];

#if defined(__CUDA_ARCH_FEAT_SM103_ALL) || defined(__CUDA_ARCH_FEAT_SM100_ALL)
#define HAS_TC 1
#endif

__device__ __forceinline__ unsigned su32(const void*p){unsigned a;
    asm("{.reg .u64 t; cvta.to.shared.u64 t,%1; cvt.u32.u64 %0,t;}":"=r"(a):"l"(p));return a;}
#define TC_ALLOC(sa,n) asm volatile("tcgen05.alloc.cta_group::1.sync.aligned.shared::cta.b32 [%0],%1;"::"r"(sa),"r"(n):"memory")
#define TC_RELINQ() asm volatile("tcgen05.relinquish_alloc_permit.cta_group::1.sync.aligned;")
#define TC_DEALLOC(t,n) asm volatile("tcgen05.dealloc.cta_group::1.sync.aligned.b32 %0,%1;"::"r"(t),"r"(n))
#define TC_COMMIT(mb) asm volatile("tcgen05.commit.cta_group::1.mbarrier::arrive::one.shared::cluster.b64 [%0];"::"r"(mb):"memory")
#define TC_FA() asm volatile("tcgen05.fence::after_thread_sync;":::"memory")
#define TC_FB() asm volatile("tcgen05.fence::before_thread_sync;":::"memory")
#define TC_WLD() asm volatile("tcgen05.wait::ld.sync.aligned;":::"memory")
#define TC_WST() asm volatile("tcgen05.wait::st.sync.aligned;":::"memory")
#define FPA() asm volatile("fence.proxy.async.shared::cta;":::"memory")
#define MBI(mb,c) asm volatile("mbarrier.init.shared.b64 [%0],%1;"::"r"(mb),"r"(c):"memory")
#define MBW(mb,ph) do{unsigned _d=0;while(!_d){asm volatile("{.reg .pred p;\n mbarrier.try_wait.parity.acquire.cta.shared::cta.b64 p,[%1],%2;\n selp.b32 %0,1,0,p;}":"=r"(_d):"r"(mb),"r"(ph):"memory");}}while(0)
#define TC_LD32(r,a) asm volatile("tcgen05.ld.sync.aligned.32x32b.x32.b32 {%0,%1,%2,%3,%4,%5,%6,%7,%8,%9,%10,%11,%12,%13,%14,%15,%16,%17,%18,%19,%20,%21,%22,%23,%24,%25,%26,%27,%28,%29,%30,%31},[%32];" \
 :"=r"((r)[0]),"=r"((r)[1]),"=r"((r)[2]),"=r"((r)[3]),"=r"((r)[4]),"=r"((r)[5]),"=r"((r)[6]),"=r"((r)[7]),"=r"((r)[8]),"=r"((r)[9]),"=r"((r)[10]),"=r"((r)[11]),"=r"((r)[12]),"=r"((r)[13]),"=r"((r)[14]),"=r"((r)[15]), \
  "=r"((r)[16]),"=r"((r)[17]),"=r"((r)[18]),"=r"((r)[19]),"=r"((r)[20]),"=r"((r)[21]),"=r"((r)[22]),"=r"((r)[23]),"=r"((r)[24]),"=r"((r)[25]),"=r"((r)[26]),"=r"((r)[27]),"=r"((r)[28]),"=r"((r)[29]),"=r"((r)[30]),"=r"((r)[31]):"r"(a))
#define TC_LD16(r,a) asm volatile("tcgen05.ld.sync.aligned.32x32b.x16.b32 {%0,%1,%2,%3,%4,%5,%6,%7,%8,%9,%10,%11,%12,%13,%14,%15},[%16];" \
 :"=r"((r)[0]),"=r"((r)[1]),"=r"((r)[2]),"=r"((r)[3]),"=r"((r)[4]),"=r"((r)[5]),"=r"((r)[6]),"=r"((r)[7]), \
  "=r"((r)[8]),"=r"((r)[9]),"=r"((r)[10]),"=r"((r)[11]),"=r"((r)[12]),"=r"((r)[13]),"=r"((r)[14]),"=r"((r)[15]):"r"(a))
#define TC_LD1(r0,a) asm volatile("tcgen05.ld.sync.aligned.32x32b.x1.b32 {%0},[%1];":"=r"(r0):"r"(a))
#define TC_ST16(a,r) asm volatile("tcgen05.st.sync.aligned.32x32b.x16.b32 [%0],{%1,%2,%3,%4,%5,%6,%7,%8,%9,%10,%11,%12,%13,%14,%15,%16};" \
 ::"r"(a),"r"((r)[0]),"r"((r)[1]),"r"((r)[2]),"r"((r)[3]),"r"((r)[4]),"r"((r)[5]),"r"((r)[6]),"r"((r)[7]),"r"((r)[8]),"r"((r)[9]),"r"((r)[10]),"r"((r)[11]),"r"((r)[12]),"r"((r)[13]),"r"((r)[14]),"r"((r)[15]):"memory")
#define SWZ(x) ((x)^(((x)>>3)&0x70))
__device__ __forceinline__ unsigned long long mkd(unsigned a){
    return ((2ull<<61)|(1ull<<46)|(64ull<<32)|(1ull<<16))|((unsigned long long)(a>>4)&0x3FFF);}
__device__ __forceinline__ void mma_ss(unsigned d,unsigned long long a,unsigned long long b,unsigned id,unsigned en){
    asm volatile("{.reg .pred p;\n setp.ne.u32 p,%5,0;\n tcgen05.mma.cta_group::1.kind::f16 [%0],%1,%2,%3,{%4,%4,%4,%4},p;}"
    ::"r"(d),"l"(a),"l"(b),"r"(id),"r"(0u),"r"(en):"memory");}
__device__ __forceinline__ void mma_ts(unsigned d,unsigned a,unsigned long long b,unsigned id,unsigned en){
    asm volatile("{.reg .pred p;\n setp.ne.u32 p,%5,0;\n tcgen05.mma.cta_group::1.kind::f16 [%0],[%1],%2,%3,{%4,%4,%4,%4},p;}"
    ::"r"(d),"r"(a),"l"(b),"r"(id),"r"(0u),"r"(en):"memory");}
__device__ __forceinline__ float ex2f(float x){float y;asm("ex2.approx.ftz.f32 %0,%1;":"=f"(y):"f"(x));return y;}
__device__ __forceinline__ float rcpf(float x){float y;asm("rcp.approx.ftz.f32 %0,%1;":"=f"(y):"f"(x));return y;}
__device__ __forceinline__ unsigned f16p(float lo,float hi){unsigned r;
    asm("cvt.rn.f16x2.f32 %0,%1,%2;":"=r"(r):"f"(hi),"f"(lo));return r;}
__device__ __forceinline__ void split2(float a,float b,unsigned&hi,unsigned&lo){
    __nv_bfloat16 ha=__float2bfloat16(a),hb=__float2bfloat16(b);
    __nv_bfloat16 la=__float2bfloat16(a-__bfloat162float(ha));
    __nv_bfloat16 lb=__float2bfloat16(b-__bfloat162float(hb));
    hi=(unsigned)*(unsigned short*)&ha|((unsigned)*(unsigned short*)&hb<<16);
    lo=(unsigned)*(unsigned short*)&la|((unsigned)*(unsigned short*)&lb<<16);
}
#define IDS 0x8100490u
#define IDS48 0x80C0490u
#define IDS16 0x8040490u
#define IDP 0x80A0010u
#define XPL 294912u
#define POS 36u

// ---------------- prep (vectorized; X via smem transpose) ----------------
__global__ void __launch_bounds__(256)
prep_all(const float* __restrict__ x,const float* __restrict__ Wq,
         const float* __restrict__ Wk,const float* __restrict__ Wv,
         const float* __restrict__ Wp){
    __shared__ float st[64*65];
    const int b=blockIdx.x,tid=threadIdx.x;
    if(b<32){
        const int z=b>>3,mh=(b>>2)&1,kc=b&3;
        const float* W=(z==0)?Wq:(z==1)?Wk:(z==2)?Wv:Wp;
        char* img=g_wsp+(unsigned)(((z*2+mh)*4+kc)*2)*16384u;
#pragma unroll
        for(int e=0;e<2;e++){
            int unit=tid+e*256,r=unit>>2,c0=(unit&3)*16;
            const float* src=W+(mh*128+r)*256+kc*64+c0;
            unsigned hw[8],lw[8];
#pragma unroll
            for(int i=0;i<4;i++){
                float4 v=*(const float4*)(src+i*4);
                split2(v.x,v.y,hw[2*i],lw[2*i]);
                split2(v.z,v.w,hw[2*i+1],lw[2*i+1]);
            }
            unsigned o0=SWZ((unsigned)(r*128+c0*2)),o1=SWZ((unsigned)(r*128+c0*2+16));
            *(uint4*)(img+o0)=make_uint4(hw[0],hw[1],hw[2],hw[3]);
            *(uint4*)(img+o1)=make_uint4(hw[4],hw[5],hw[6],hw[7]);
            *(uint4*)(img+16384+o0)=make_uint4(lw[0],lw[1],lw[2],lw[3]);
            *(uint4*)(img+16384+o1)=make_uint4(lw[4],lw[5],lw[6],lw[7]);
        }
    }else{
        const int q=b-32,nt=q>>2,kc=q&3;
        char* hip=g_xt+(unsigned)(kc*2)*XPL;
        char* lop=hip+XPL;
#pragma unroll
        for(int e=0;e<4;e++){
            int lin=tid+e*256,c=lin>>4,g4=(lin&15)*4;
            float4 v=*(const float4*)(x+(kc*64+c)*NDIM+nt*64+g4);
            st[c*65+g4]=v.x; st[c*65+g4+1]=v.y; st[c*65+g4+2]=v.z; st[c*65+g4+3]=v.w;
        }
        __syncthreads();
        const int g=tid>>2,c0=(tid&3)*16;
        unsigned hw[8],lw[8];
#pragma unroll
        for(int i=0;i<8;i++)
            split2(st[(c0+2*i)*65+g],st[(c0+2*i+1)*65+g],hw[i],lw[i]);
        unsigned gg=(unsigned)(nt*64+g)*128u+(unsigned)c0*2u;
        unsigned o0=SWZ(gg),o1=SWZ(gg+16);
        *(uint4*)(hip+o0)=make_uint4(hw[0],hw[1],hw[2],hw[3]);
        *(uint4*)(hip+o1)=make_uint4(hw[4],hw[5],hw[6],hw[7]);
        *(uint4*)(lop+o0)=make_uint4(lw[0],lw[1],lw[2],lw[3]);
        *(uint4*)(lop+o1)=make_uint4(lw[4],lw[5],lw[6],lw[7]);
    }
}

// ---------------- QKV GEMM: 128o x 48n tiles (R16, unchanged) ----------------
#define CHS 45056
#define GM_SZ 90176
__global__ void __launch_bounds__(256,2)
tc_gemm(const char* __restrict__ Ab,const char* __restrict__ Bb,
        const float* __restrict__ b0,const float* __restrict__ b1,
        const float* __restrict__ b2){
    const int z=blockIdx.z,mh=blockIdx.y,nt=blockIdx.x,tid=threadIdx.x;
    const float* bb=(z==0)?b0:(z==1)?b1:b2;
#ifdef HAS_TC
    extern __shared__ char sm[];
    const unsigned smb=su32(sm);
    const int wid=tid>>5,lid=tid&31;
    if(wid==0){ TC_ALLOC(smb+90112,128); TC_RELINQ(); }
    if(tid==0){ MBI(smb+90120,1); MBI(smb+90128,1); }
    const char* Abase=Ab+(unsigned)((z*2+mh)*4*2)*16384u;
#pragma unroll
    for(int i=0;i<8;i++) *(uint4*)(sm+tid*16+i*4096)=*(const uint4*)(Abase+tid*16+i*4096);
    {
        const char* hip=Bb+(unsigned)nt*6144u;
#pragma unroll
        for(int i=0;i<3;i++){
            unsigned off=tid*16+i*4096;
            const char* src=(off<6144u)?(hip+off):(hip+XPL+off-6144u);
            *(uint4*)(sm+32768+off)=*(const uint4*)src;
        }
    }
    FPA(); __syncthreads();
    unsigned tmem; asm volatile("ld.shared.b32 %0,[%1];":"=r"(tmem):"r"(smb+90112));
#pragma unroll
    for(int kc=0;kc<4;kc++){
        const unsigned bo=(kc&1)*CHS;
        if(tid==0){
            unsigned long long ah=mkd(smb+bo),al=ah+1024;
            unsigned long long bh=mkd(smb+bo+32768),bl=bh+384;
#pragma unroll
            for(int ks=0;ks<4;ks++){
                unsigned long long o2=ks*2;
                mma_ss(tmem,ah+o2,bh+o2,IDS48,(kc|ks)!=0);
                mma_ss(tmem,ah+o2,bl+o2,IDS48,1);
                mma_ss(tmem,al+o2,bh+o2,IDS48,1);
            }
            TC_COMMIT(smb+90120+8*(kc&1));
        }
        if(kc<3){
            uint4 ar[8],br[3];
            const char* An=Abase+(unsigned)(kc+1)*32768u;
#pragma unroll
            for(int i=0;i<8;i++) ar[i]=*(const uint4*)(An+tid*16+i*4096);
            const char* hip=Bb+(unsigned)(kc+1)*2*XPL+(unsigned)nt*6144u;
#pragma unroll
            for(int i=0;i<3;i++){
                unsigned off=tid*16+i*4096;
                br[i]=*(const uint4*)((off<6144u)?(hip+off):(hip+XPL+off-6144u));
            }
            if(kc>=1) MBW(smb+90120+8*((kc-1)&1),((kc-1)>>1)&1);
            const unsigned nb=((kc+1)&1)*CHS;
#pragma unroll
            for(int i=0;i<8;i++) *(uint4*)(sm+nb+tid*16+i*4096)=ar[i];
#pragma unroll
            for(int i=0;i<3;i++) *(uint4*)(sm+nb+32768+tid*16+i*4096)=br[i];
            FPA(); __syncthreads();
        }
    }
    MBW(smb+90128,1);
    TC_FA();
    const int sp=wid&3,hf=wid>>2;
    if(hf==0){
        unsigned sr[48];
        TC_LD32(sr,tmem+((unsigned)sp<<21));
        TC_LD16(sr+32,tmem+32+((unsigned)sp<<21));
        TC_WLD();
        const int o=mh*128+sp*32+lid;
        const float bv=bb[o];
        if(z==2){
            unsigned hw[24];
#pragma unroll
            for(int jj=0;jj<24;jj++)
                hw[jj]=f16p(__uint_as_float(sr[2*jj])+bv,__uint_as_float(sr[2*jj+1])+bv);
            uint4* dst=(uint4*)(g_vh+(unsigned)o*NDIM+nt*48);
#pragma unroll
            for(int i=0;i<6;i++) dst[i]=make_uint4(hw[4*i],hw[4*i+1],hw[4*i+2],hw[4*i+3]);
        }else{
            const float CQ=0.17677669529663687f*1.4426950408889634f;
            const float cm=(z==0)?CQ:1.f;
            __nv_bfloat16* stg=(__nv_bfloat16*)sm;
#pragma unroll
            for(int j=0;j<48;j++){
                float vv=(__uint_as_float(sr[j])+bv)*cm;
                __nv_bfloat16 hi=__float2bfloat16(vv);
                stg[(j*4+sp)*64+lid]=hi;
                stg[(j*4+sp)*64+32+lid]=__float2bfloat16(vv-__bfloat162float(hi));
            }
        }
    }
    __syncthreads();
    if(z<2){
        const __nv_bfloat16* stg=(const __nv_bfloat16*)sm;
#pragma unroll
        for(int e=0;e<2;e++){
            int idx=tid+e*256;
            if(idx<384){
                int r=idx>>3,p=(idx&7)>>1,hh=idx&1;
                __nv_bfloat16* dst=((z==0)?g_qp:g_kp)+(unsigned)(mh*4+p)*(NDIM*64)
                                   +(unsigned)(nt*48+r)*64+hh*32;
                const uint4* src=(const uint4*)(stg+(r*4+p)*64+hh*32);
#pragma unroll
                for(int i=0;i<4;i++) ((uint4*)dst)[i]=src[i];
            }
        }
    }
    __syncthreads();
    if(wid==0) TC_DEALLOC(tmem,128);
#else
    for(int it=tid;it<6144;it+=256){
        int oL=it/48,j=it%48,o=mh*128+oL,n=nt*48+j;
        float acc=0.f;
        for(int kc=0;kc<4;kc++){
            const char* Ai=Ab+(unsigned)(((z*2+mh)*4+kc)*2)*16384u;
            const char* hip=Bb+(unsigned)(kc*2)*XPL;
            for(int c=0;c<64;c++){
                unsigned ao=SWZ((unsigned)(oL*128+c*2)),bo2=SWZ((unsigned)(n*128+c*2));
                float a=__bfloat162float(*(const __nv_bfloat16*)(Ai+ao))
                       +__bfloat162float(*(const __nv_bfloat16*)(Ai+16384+ao));
                float bvv=__bfloat162float(*(const __nv_bfloat16*)(hip+bo2))
                         +__bfloat162float(*(const __nv_bfloat16*)(hip+XPL+bo2));
                acc+=a*bvv;
            }
        }
        float val=acc+bb[o];
        if(z==2) g_vh[o*NDIM+n]=__float2half(val);
        else{
            const float CQ=0.17677669529663687f*1.4426950408889634f;
            float vv=val*((z==0)?CQ:1.f);
            __nv_bfloat16 hi=__float2bfloat16(vv);
            __nv_bfloat16* base=((z==0)?g_qp:g_kp)+(o>>5)*(NDIM*64);
            base[n*64+(o&31)]=hi;
            base[n*64+32+(o&31)]=__float2bfloat16(vv-__bfloat162float(hi));
        }
    }
#endif
}

// ---------------- proj GEMM: 128o x 16n tiles (R16 + float4 epilogue) ----------------
#define PCHS 40960
#define PM_SZ 81984
__global__ void __launch_bounds__(256,2)
tc_proj(const char* __restrict__ Ab,const float* __restrict__ bp,
        float* __restrict__ outp){
    const int mh=blockIdx.y,nt4=blockIdx.x,tid=threadIdx.x;
#ifdef HAS_TC
    extern __shared__ char sm[];
    const unsigned smb=su32(sm);
    const int wid=tid>>5,lid=tid&31;
    if(wid==0){ TC_ALLOC(smb+81920,128); TC_RELINQ(); }
    if(tid==0){ MBI(smb+81928,1); MBI(smb+81936,1); }
    const char* Abase=Ab+(unsigned)((6+mh)*4*2)*16384u;
    const int nloc=tid>>4,c0=(tid&15)*4;
    const int npo=nt4*16+nloc,qt=npo>>7,nl=npo&127;
#pragma unroll
    for(int i=0;i<8;i++) *(uint4*)(sm+tid*16+i*4096)=*(const uint4*)(Abase+tid*16+i*4096);
    {
        int gc=c0,Hh=gc>>5,d0=gc&31;
        const float* p0=g_po+(unsigned)(((qt*8+Hh)*2+0)*128+nl)*POS;
        const float* p1=g_po+(unsigned)(((qt*8+Hh)*2+1)*128+nl)*POS;
        float inv=rcpf(p0[32]+p1[32]);
#pragma unroll
        for(int i=0;i<4;i++){
            float v=(p0[d0+i]+p1[d0+i])*inv;
            __nv_bfloat16 hi=__float2bfloat16(v);
            unsigned off=SWZ((unsigned)(nloc*128+(c0+i)*2));
            *(__nv_bfloat16*)(sm+32768+off)=hi;
            *(__nv_bfloat16*)(sm+32768+2048+off)=__float2bfloat16(v-__bfloat162float(hi));
        }
    }
    FPA(); __syncthreads();
    unsigned tmem; asm volatile("ld.shared.b32 %0,[%1];":"=r"(tmem):"r"(smb+81920));
#pragma unroll
    for(int kc=0;kc<4;kc++){
        const unsigned bo=(kc&1)*PCHS;
        if(tid==0){
            unsigned long long ah=mkd(smb+bo),al=ah+1024;
            unsigned long long bh=mkd(smb+bo+32768),bl=bh+128;
#pragma unroll
            for(int ks=0;ks<4;ks++){
                unsigned long long o2=ks*2;
                mma_ss(tmem,ah+o2,bh+o2,IDS16,(kc|ks)!=0);
                mma_ss(tmem,ah+o2,bl+o2,IDS16,1);
                mma_ss(tmem,al+o2,bh+o2,IDS16,1);
            }
            TC_COMMIT(smb+81928+8*(kc&1));
        }
        if(kc<3){
            uint4 ar[8];
            const char* An=Abase+(unsigned)(kc+1)*32768u;
#pragma unroll
            for(int i=0;i<8;i++) ar[i]=*(const uint4*)(An+tid*16+i*4096);
            int gc=(kc+1)*64+c0,Hh=gc>>5,d0=gc&31;
            const float* p0=g_po+(unsigned)(((qt*8+Hh)*2+0)*128+nl)*POS;
            const float* p1=g_po+(unsigned)(((qt*8+Hh)*2+1)*128+nl)*POS;
            float inv=rcpf(p0[32]+p1[32]);
            float pv[4];
#pragma unroll
            for(int i=0;i<4;i++) pv[i]=(p0[d0+i]+p1[d0+i])*inv;
            if(kc>=1) MBW(smb+81928+8*((kc-1)&1),((kc-1)>>1)&1);
            const unsigned nb=((kc+1)&1)*PCHS;
#pragma unroll
            for(int i=0;i<8;i++) *(uint4*)(sm+nb+tid*16+i*4096)=ar[i];
#pragma unroll
            for(int i=0;i<4;i++){
                __nv_bfloat16 hi=__float2bfloat16(pv[i]);
                unsigned off=SWZ((unsigned)(nloc*128+(c0+i)*2));
                *(__nv_bfloat16*)(sm+nb+32768+off)=hi;
                *(__nv_bfloat16*)(sm+nb+32768+2048+off)=__float2bfloat16(pv[i]-__bfloat162float(hi));
            }
            FPA(); __syncthreads();
        }
    }
    MBW(smb+81936,1);
    TC_FA();
    const int sp=wid&3,hf=wid>>2;
    if(hf==0){
        unsigned sr[16];
        TC_LD16(sr,tmem+((unsigned)sp<<21)); TC_WLD();
        const int o=mh*128+sp*32+lid;
        const float bv=bp[o];
        float4* dst=(float4*)(outp+(unsigned)o*NDIM+nt4*16);
#pragma unroll
        for(int j4=0;j4<4;j4++)
            dst[j4]=make_float4(__uint_as_float(sr[4*j4])+bv,__uint_as_float(sr[4*j4+1])+bv,
                                __uint_as_float(sr[4*j4+2])+bv,__uint_as_float(sr[4*j4+3])+bv);
    }
    __syncthreads();
    if(wid==0) TC_DEALLOC(tmem,128);
#else
    for(int it=tid;it<2048;it+=256){
        int oL=it>>4,j=it&15,o=mh*128+oL,n=nt4*16+j;
        float acc=0.f;
        for(int kc=0;kc<4;kc++){
            const char* Ai=Ab+(unsigned)(((6+mh)*4+kc)*2)*16384u;
            for(int c=0;c<64;c++){
                unsigned ao=SWZ((unsigned)(oL*128+c*2));
                float a=__bfloat162float(*(const __nv_bfloat16*)(Ai+ao))
                       +__bfloat162float(*(const __nv_bfloat16*)(Ai+16384+ao));
                int qt2=n>>7,nl2=n&127,cg2=kc*64+c,Hh=cg2>>5,d=cg2&31;
                const float* p0=g_po+(unsigned)(((qt2*8+Hh)*2+0)*128+nl2)*POS;
                const float* p1=g_po+(unsigned)(((qt2*8+Hh)*2+1)*128+nl2)*POS;
                acc+=a*(p0[d]+p1[d])/(p0[32]+p1[32]);
            }
        }
        outp[o*NDIM+n]=acc+bp[o];
    }
#endif
}

// ---------------- attention: split-KV + pipelined S (R16 + uint4 epilogue) ----------------
#define SM_B 64
#define SM_Q 36864
#define SM_K 53248
#define SM_V 77824
#define SM_TOT 98304
#define TPC 18

#ifdef HAS_TC
__device__ __forceinline__ void issue_s(unsigned tmem,unsigned smb,int t){
    unsigned long long kd=mkd(smb+SM_K+(t%3)*8192);
    unsigned long long qd=mkd(smb+SM_Q);
    unsigned tS=tmem+64+(t&1)*64;
    mma_ss(tS,qd+0,kd+0,IDS,0); mma_ss(tS,qd+2,kd+2,IDS,1);
    mma_ss(tS,qd+0,kd+4,IDS,1); mma_ss(tS,qd+2,kd+6,IDS,1);
    mma_ss(tS,qd+4,kd+0,IDS,1); mma_ss(tS,qd+6,kd+2,IDS,1);
    TC_COMMIT(smb+8+8*(t&1));
}
#endif

__global__ void __launch_bounds__(256,2)
attn_kernel(const float* __restrict__ emb){
    extern __shared__ char sm[];
#ifdef HAS_TC
    const unsigned smb=su32(sm);
    const int tid=threadIdx.x,wid=tid>>5,lid=tid&31;
    const int H=blockIdx.y,n0=blockIdx.x*128,half=blockIdx.z;
    const int tbase=half*TPC;
    float* bias=(float*)(sm+SM_B);
    if(wid==0){ TC_ALLOC(smb,256); TC_RELINQ(); }
    if(tid==0){MBI(smb+8,1);MBI(smb+16,1);MBI(smb+24,1);MBI(smb+32,1);}
    for(int i=tid;i<9025;i+=256){
        int a=i/95,b=i-a*95,dx=a-47,dy=b-47;
        if(dx<0)dx=-dx; if(dy<0)dy=-dy;
        bias[i]=(dx<=5&&dy<=5)?emb[(dx*6+dy)*8+H]*1.4426950408889634f:0.f;
    }
    const __nv_bfloat16* qp=g_qp+H*(NDIM*64);
    const __nv_bfloat16* kp=g_kp+H*(NDIM*64);
#pragma unroll
    for(int e=0;e<4;e++){
        int idx=tid+e*256,r=idx>>3,c=(idx&7)*16;
        uint4 v=*(const uint4*)((const char*)(qp+(n0+r)*64)+c);
        *(uint4*)(sm+SM_Q+SWZ(r*128+c))=v;
    }
    {
        int b=tid>>6,i=tid&63,d=32+(i>>3),c=(i&7)*16;
        unsigned w=(d==32)?0x3C003C00u:0u;
        *(uint4*)(sm+SM_V+b*5120+SWZ(d*128+c))=make_uint4(w,w,w,w);
    }
    const int lj=tid>>3, lc=(tid&7)*16, ld=tid>>3;
#pragma unroll
    for(int t=0;t<2;t++){
        int m0=(tbase+t)*64;
        uint4 k0=*(const uint4*)((const char*)(kp+(m0+lj)*64)+lc);
        uint4 k1=*(const uint4*)((const char*)(kp+(m0+lj+32)*64)+lc);
        uint4 vv=*(const uint4*)((const char*)(g_vh+(H*32+ld)*NDIM+m0)+lc);
        *(uint4*)(sm+SM_K+t*8192+SWZ(lj*128+lc))=k0;
        *(uint4*)(sm+SM_K+t*8192+SWZ((lj+32)*128+lc))=k1;
        *(uint4*)(sm+SM_V+t*5120+SWZ(ld*128+lc))=vv;
    }
    FPA(); __syncthreads();
    unsigned tmem; asm volatile("ld.shared.b32 %0,[%1];":"=r"(tmem):"r"(smb));
    if(tid==0) issue_s(tmem,smb,0);
    const int sp=wid&3,hf=wid>>2;
    const unsigned spoff=(unsigned)sp<<21;
    const int n=n0+sp*32+lid,xn=n/48,yn=n-xn*48;
    const float* bp=bias+xn*95+yn+4512;

    for(int t=0;t<TPC;t++){
        if(t<TPC-1&&tid==0) issue_s(tmem,smb,t+1);
        uint4 k0,k1,vv; const bool pf=(t<TPC-2);
        if(pf){
            int m0=(tbase+t+2)*64;
            k0=*(const uint4*)((const char*)(kp+(m0+lj)*64)+lc);
            k1=*(const uint4*)((const char*)(kp+(m0+lj+32)*64)+lc);
            vv=*(const uint4*)((const char*)(g_vh+(H*32+ld)*NDIM+m0)+lc);
        }
        if(t>=2) MBW(smb+24+8*(t&1),((t-2)>>1)&1);
        MBW(smb+8+8*(t&1),(t>>1)&1); TC_FA();
        unsigned sr[32];
        TC_LD32(sr,tmem+64+(t&1)*64+hf*32+spoff); TC_WLD();
        const int mc=(tbase+t)*64+hf*32;
        unsigned pk[16];
#pragma unroll
        for(int jj=0;jj<16;jj++){
            int m0_=mc+2*jj,m1_=m0_+1;
            int x0=(m0_*2731)>>17,x1=(m1_*2731)>>17;
            float p0=ex2f(__uint_as_float(sr[2*jj])+bp[-(m0_+47*x0)]);
            float p1=ex2f(__uint_as_float(sr[2*jj+1])+bp[-(m1_+47*x1)]);
            pk[jj]=f16p(p0,p1);
        }
        const unsigned pbase=tmem+192+(t&1)*32;
        TC_ST16(pbase+hf*16+spoff,pk); TC_WST();
        if(pf){
            int ko=SM_K+((t+2)%3)*8192, vo=SM_V+((t+2)%4)*5120;
            *(uint4*)(sm+ko+SWZ(lj*128+lc))=k0;
            *(uint4*)(sm+ko+SWZ((lj+32)*128+lc))=k1;
            *(uint4*)(sm+vo+SWZ(ld*128+lc))=vv;
        }
        TC_FB(); FPA(); __syncthreads();
        if(tid==0){
            TC_FA();
            unsigned long long vd=mkd(smb+SM_V+(t%4)*5120);
#pragma unroll
            for(int k=0;k<4;k++) mma_ts(tmem,pbase+k*8,vd+k*2,IDP,(t+k)>0);
            TC_COMMIT(smb+24+8*(t&1));
        }
    }
    MBW(smb+24,0); MBW(smb+32,0);
    TC_FA();
    if(hf==0){
        unsigned od[32],lr;
        TC_LD32(od,tmem+spoff); TC_LD1(lr,tmem+32+spoff); TC_WLD();
        float* po=g_po+(unsigned)(((blockIdx.x*8+H)*2+half)*128+sp*32+lid)*POS;
#pragma unroll
        for(int i=0;i<8;i++)
            *(uint4*)(po+i*4)=make_uint4(od[4*i],od[4*i+1],od[4*i+2],od[4*i+3]);
        po[32]=__uint_as_float(lr);
    }
    __syncthreads();
    if(wid==0) TC_DEALLOC(tmem,256);
#else
    const int tid=threadIdx.x,H=blockIdx.y,n0=blockIdx.x*128,half=blockIdx.z;
    if(tid<128){
        int n=n0+tid,xn=n/48,yn=n-48*xn;
        const __nv_bfloat16* qr=g_qp+H*(NDIM*64)+n*64;
        float qv[32],o[32],l=0.f;
#pragma unroll
        for(int d=0;d<32;d++){qv[d]=__bfloat162float(qr[d])+__bfloat162float(qr[32+d]);o[d]=0.f;}
        for(int mt=0;mt<TPC*64;mt++){
            int m=half*TPC*64+mt;
            const __nv_bfloat16* kr=g_kp+H*(NDIM*64)+m*64;
            float s=0.f;
            for(int d=0;d<32;d++) s+=qv[d]*(__bfloat162float(kr[d])+__bfloat162float(kr[32+d]));
            int xm=m/48,ym=m-48*xm,dx=xn-xm,dy=yn-ym;
            if(dx<0)dx=-dx; if(dy<0)dy=-dy;
            float b=(dx<6&&dy<6)?emb[(dx*6+dy)*8+H]*1.4426950408889634f:0.f;
            float p=exp2f(s+b); l+=p;
            for(int d=0;d<32;d++) o[d]+=p*__half2float(g_vh[(H*32+d)*NDIM+m]);
        }
        float* po=g_po+(unsigned)(((blockIdx.x*8+H)*2+half)*128+tid)*POS;
        for(int d=0;d<32;d++) po[d]=o[d];
        po[32]=l;
    }
#endif
}

extern "C" void kernel_launch(void* const* d_in,const int* in_sizes,int n_in,
                              void* d_out,int out_size){
    const float* x  =(const float*)d_in[0];
    const float* Wq =(const float*)d_in[1]; const float* bq=(const float*)d_in[2];
    const float* Wk =(const float*)d_in[3]; const float* bk=(const float*)d_in[4];
    const float* Wv =(const float*)d_in[5]; const float* bv=(const float*)d_in[6];
    const float* Wp =(const float*)d_in[7]; const float* bp=(const float*)d_in[8];
    const float* emb=(const float*)d_in[9];
    float* out=(float*)d_out;
    char* wsp; char* xt;
    cudaGetSymbolAddress((void**)&wsp,g_wsp);
    cudaGetSymbolAddress((void**)&xt,g_xt);
    cudaFuncSetAttribute(tc_gemm,cudaFuncAttributeMaxDynamicSharedMemorySize,GM_SZ);
    cudaFuncSetAttribute(tc_proj,cudaFuncAttributeMaxDynamicSharedMemorySize,PM_SZ);
    cudaFuncSetAttribute(attn_kernel,cudaFuncAttributeMaxDynamicSharedMemorySize,SM_TOT);
    prep_all<<<176,256>>>(x,Wq,Wk,Wv,Wp);
    tc_gemm<<<dim3(48,2,3),256,GM_SZ>>>(wsp,xt,bq,bk,bv);
    attn_kernel<<<dim3(18,HEADS,2),256,SM_TOT>>>(emb);
    tc_proj<<<dim3(144,2),256,PM_SZ>>>(wsp,bp,out);
}